// round 5
// baseline (speedup 1.0000x reference)
#include <cuda_runtime.h>
#include <cuda_fp16.h>
#include <cstdint>
#include <cstddef>

// ---------------------------------------------------------------------------
// Problem constants
// ---------------------------------------------------------------------------
#define NHEADS   12
#define DHEAD    32
#define NTOK     49
#define DIM      384
#define BN_TOTAL 4096
#define TOKENS   (BN_TOTAL * NTOK)   // 200704
#define QKV_COLS 1152

// Scratch (allocation-free rule: device globals)
__device__ float  g_qkv[(size_t)TOKENS * QKV_COLS];   // fp32 qkv for attention
__device__ __half g_xH[(size_t)TOKENS * DIM];
__device__ __half g_xL[(size_t)TOKENS * DIM];
__device__ __half g_ctxH[(size_t)TOKENS * DIM];
__device__ __half g_ctxL[(size_t)TOKENS * DIM];
__device__ __half g_wqkvH[(size_t)QKV_COLS * DIM];
__device__ __half g_wqkvL[(size_t)QKV_COLS * DIM];
__device__ __half g_wprojH[(size_t)DIM * DIM];
__device__ __half g_wprojL[(size_t)DIM * DIM];

// ---------------------------------------------------------------------------
// Common device helpers
// ---------------------------------------------------------------------------
__device__ __forceinline__ void split2(float x, float y, uint32_t& hi, uint32_t& lo) {
    half2 h = __floats2half2_rn(x, y);
    float rx = x - __low2float(h);
    float ry = y - __high2float(h);
    half2 l = __floats2half2_rn(rx, ry);
    hi = *(uint32_t*)&h;
    lo = *(uint32_t*)&l;
}

__device__ __forceinline__ void mma_f16(float* d, const uint32_t* a, const uint32_t* b) {
    asm volatile(
        "mma.sync.aligned.m16n8k16.row.col.f32.f16.f16.f32 "
        "{%0,%1,%2,%3}, {%4,%5,%6,%7}, {%8,%9}, {%0,%1,%2,%3};"
        : "+f"(d[0]), "+f"(d[1]), "+f"(d[2]), "+f"(d[3])
        : "r"(a[0]), "r"(a[1]), "r"(a[2]), "r"(a[3]), "r"(b[0]), "r"(b[1]));
}

__device__ __forceinline__ void ldmx4(uint32_t* r, uint32_t addr) {
    asm volatile("ldmatrix.sync.aligned.m8n8.x4.shared.b16 {%0,%1,%2,%3}, [%4];"
        : "=r"(r[0]), "=r"(r[1]), "=r"(r[2]), "=r"(r[3]) : "r"(addr));
}

__device__ __forceinline__ uint32_t smem_u32(const void* p) {
    uint32_t a;
    asm("{ .reg .u64 t; cvta.to.shared.u64 t, %1; cvt.u32.u64 %0, t; }"
        : "=r"(a) : "l"(p));
    return a;
}

#define CP_ASYNC16(dst, src) \
    asm volatile("cp.async.cg.shared.global [%0], [%1], 16;" :: "r"(dst), "l"(src))
#define CP_COMMIT() asm volatile("cp.async.commit_group;" ::: "memory")
#define CP_WAIT(n)  asm volatile("cp.async.wait_group %0;" :: "n"(n) : "memory")

// ---------------------------------------------------------------------------
// Prep: split fp32 -> fp16 hi/lo planes (grid-stride, float4 granularity)
// ---------------------------------------------------------------------------
__global__ void split_kernel(const float* __restrict__ src,
                             __half* __restrict__ hi, __half* __restrict__ lo,
                             size_t n4)
{
    const size_t stride = (size_t)gridDim.x * blockDim.x;
    for (size_t i = (size_t)blockIdx.x * blockDim.x + threadIdx.x; i < n4; i += stride) {
        float4 v = *((const float4*)src + i);
        uint32_t h01, l01, h23, l23;
        split2(v.x, v.y, h01, l01);
        split2(v.z, v.w, h23, l23);
        *(uint2*)(hi + i * 4) = make_uint2(h01, h23);
        *(uint2*)(lo + i * 4) = make_uint2(l01, l23);
    }
}

// ---------------------------------------------------------------------------
// fp16 hi/lo GEMM (NT): C = (AH+AL)(BH+BL)^T + bias, 3-term MMA.
// BM=BN=128, BK=16, double-buffered cp.async, ldmatrix fragments.
// smem row stride = 24 halves (48B): conflict-free for ldmatrix & staging.
// ---------------------------------------------------------------------------
#define GBM 128
#define GBK 16
#define RSTRIDE 24                     // halves per smem row
#define PLANE_BYTES (128 * RSTRIDE * 2)   // 6144
#define BUF_BYTES   (4 * PLANE_BYTES)     // 24576
#define SM_GEMM_TOTAL (2 * BUF_BYTES)     // 49152

__global__ __launch_bounds__(256, 2)
void gemm_hilo_nt(const __half* __restrict__ AH, const __half* __restrict__ AL,
                  const __half* __restrict__ BH, const __half* __restrict__ BL,
                  const float* __restrict__ bias, float* __restrict__ C,
                  int M, int N, int K)
{
    extern __shared__ char sm[];
    const uint32_t smb = smem_u32(sm);

    const int tid  = threadIdx.x;
    const int wid  = tid >> 5;
    const int lane = tid & 31;
    const int g = lane >> 2;
    const int c = lane & 3;
    const int wm = wid & 1;
    const int wn = wid >> 1;

    const int m0 = blockIdx.y * GBM;
    const int n0 = blockIdx.x * GBM;

    // staging: thread t stages chunk t of each plane: row r=t>>1, half8 c2=t&1
    const int sr  = tid >> 1;
    const int sc2 = tid & 1;
    const __half* gA_H = AH + (size_t)(m0 + sr) * K + sc2 * 8;
    const __half* gA_L = AL + (size_t)(m0 + sr) * K + sc2 * 8;
    const __half* gB_H = BH + (size_t)(n0 + sr) * K + sc2 * 8;
    const __half* gB_L = BL + (size_t)(n0 + sr) * K + sc2 * 8;
    const uint32_t dstRow = smb + (uint32_t)sr * 48 + (uint32_t)sc2 * 16;

    // ldmatrix lane addressing
    const int m_idx = lane >> 3;
    const int rin   = lane & 7;
    // A: row = wm*64 + tm*16 + (m_idx&1)*8 + rin ; kbyte = (m_idx>>1)*16
    const uint32_t aRowOff = (uint32_t)(wm * 64 + (m_idx & 1) * 8 + rin) * 48
                           + (uint32_t)(m_idx >> 1) * 16;
    // B: row = wn*32 + pair*16 + (m_idx>>1)*8 + rin ; kbyte = (m_idx&1)*16
    const uint32_t bRowOff = (uint32_t)(wn * 32 + (m_idx >> 1) * 8 + rin) * 48
                           + (uint32_t)(m_idx & 1) * 16;

    float acc[4][4][4];
    #pragma unroll
    for (int i = 0; i < 4; i++)
        #pragma unroll
        for (int j = 0; j < 4; j++)
            #pragma unroll
            for (int r = 0; r < 4; r++) acc[i][j][r] = 0.f;

    const int NK = K / GBK;

    // ---- stage chunk 0 into buffer 0 ----
    {
        const size_t go = 0;
        CP_ASYNC16(dstRow + 0 * PLANE_BYTES, gA_H + go);
        CP_ASYNC16(dstRow + 1 * PLANE_BYTES, gA_L + go);
        CP_ASYNC16(dstRow + 2 * PLANE_BYTES, gB_H + go);
        CP_ASYNC16(dstRow + 3 * PLANE_BYTES, gB_L + go);
        CP_COMMIT();
    }

    for (int kt = 0; kt < NK; kt++) {
        const int cur = kt & 1;
        const uint32_t bufB = smb + (uint32_t)cur * BUF_BYTES;

        if (kt + 1 < NK) {
            const uint32_t nb = smb + (uint32_t)(cur ^ 1) * BUF_BYTES;
            const size_t go = (size_t)(kt + 1) * GBK;
            CP_ASYNC16(nb + (dstRow - smb) + 0 * PLANE_BYTES, gA_H + go);
            CP_ASYNC16(nb + (dstRow - smb) + 1 * PLANE_BYTES, gA_L + go);
            CP_ASYNC16(nb + (dstRow - smb) + 2 * PLANE_BYTES, gB_H + go);
            CP_ASYNC16(nb + (dstRow - smb) + 3 * PLANE_BYTES, gB_L + go);
            CP_COMMIT();
            CP_WAIT(1);
        } else {
            CP_WAIT(0);
        }
        __syncthreads();

        // fragments
        uint32_t bHf[4][2], bLf[4][2], af[4][4];
        #pragma unroll
        for (int p = 0; p < 2; p++) {
            uint32_t r4[4];
            ldmx4(r4, bufB + 2 * PLANE_BYTES + bRowOff + (uint32_t)p * 16 * 48);
            bHf[2 * p][0] = r4[0]; bHf[2 * p][1] = r4[1];
            bHf[2 * p + 1][0] = r4[2]; bHf[2 * p + 1][1] = r4[3];
            ldmx4(r4, bufB + 3 * PLANE_BYTES + bRowOff + (uint32_t)p * 16 * 48);
            bLf[2 * p][0] = r4[0]; bLf[2 * p][1] = r4[1];
            bLf[2 * p + 1][0] = r4[2]; bLf[2 * p + 1][1] = r4[3];
        }
        #pragma unroll
        for (int tm = 0; tm < 4; tm++)
            ldmx4(af[tm], bufB + 0 * PLANE_BYTES + aRowOff + (uint32_t)tm * 16 * 48);

        #pragma unroll
        for (int tm = 0; tm < 4; tm++)
            #pragma unroll
            for (int tn = 0; tn < 4; tn++) {
                mma_f16(acc[tm][tn], af[tm], bHf[tn]);
                mma_f16(acc[tm][tn], af[tm], bLf[tn]);
            }

        #pragma unroll
        for (int tm = 0; tm < 4; tm++)
            ldmx4(af[tm], bufB + 1 * PLANE_BYTES + aRowOff + (uint32_t)tm * 16 * 48);

        #pragma unroll
        for (int tm = 0; tm < 4; tm++)
            #pragma unroll
            for (int tn = 0; tn < 4; tn++)
                mma_f16(acc[tm][tn], af[tm], bHf[tn]);

        __syncthreads();
    }

    // ---- epilogue: bias + fp32 store ----
    #pragma unroll
    for (int tm = 0; tm < 4; tm++) {
        const int r = m0 + wm * 64 + tm * 16 + g;
        #pragma unroll
        for (int tn = 0; tn < 4; tn++) {
            const int col = n0 + wn * 32 + tn * 8 + 2 * c;
            const float b0 = __ldg(&bias[col]);
            const float b1 = __ldg(&bias[col + 1]);
            float2 o0 = make_float2(acc[tm][tn][0] + b0, acc[tm][tn][1] + b1);
            float2 o1 = make_float2(acc[tm][tn][2] + b0, acc[tm][tn][3] + b1);
            *(float2*)(C + (size_t)r * N + col)       = o0;
            *(float2*)(C + (size_t)(r + 8) * N + col) = o1;
        }
    }
}

// ---------------------------------------------------------------------------
// Fused windowed attention: vectorized QK / PV, writes ctx hi/lo fp16 planes.
// ---------------------------------------------------------------------------
#define QPAD 44   // float row stride for sq/sk/sv: conflict-free float4 access
__global__ __launch_bounds__(256) void attn_kernel(
    const float* __restrict__ mask,
    const float* __restrict__ bias_table,
    __half* __restrict__ ctxH, __half* __restrict__ ctxL)
{
    __shared__ float sq[NTOK][QPAD];
    __shared__ float sk[52][QPAD];      // rows 49..51 never written (guarded reads ok)
    __shared__ float sv[NTOK][QPAD];
    __shared__ float ss[NTOK][52];

    const int b  = blockIdx.x;
    const int bn = b / NHEADS;
    const int h  = b - bn * NHEADS;
    const int tid = threadIdx.x;

    const float* base = g_qkv + (size_t)bn * NTOK * QKV_COLS + h * DHEAD;
    for (int e = tid; e < NTOK * DHEAD; e += 256) {
        const int r = e >> 5, cc = e & 31;
        const float* p = base + (size_t)r * QKV_COLS + cc;
        sq[r][cc] = p[0];
        sk[r][cc] = p[DIM];
        sv[r][cc] = p[2 * DIM];
    }
    __syncthreads();

    const float scale = 0.17677669529663687f;
    const int win = bn >> 6;
    const float* mrow = mask + (size_t)win * (NTOK * NTOK);

    // QK^T: unit = (i, j-group of 4); 49*13 units
    for (int u = tid; u < NTOK * 13; u += 256) {
        const int i  = u / 13;
        const int j0 = (u - i * 13) * 4;
        float a0 = 0.f, a1 = 0.f, a2 = 0.f, a3 = 0.f;
        #pragma unroll
        for (int kk = 0; kk < DHEAD; kk += 4) {
            const float4 q = *(const float4*)&sq[i][kk];
            const float4 k0 = *(const float4*)&sk[j0 + 0][kk];
            const float4 k1 = *(const float4*)&sk[j0 + 1][kk];
            const float4 k2 = *(const float4*)&sk[j0 + 2][kk];
            const float4 k3 = *(const float4*)&sk[j0 + 3][kk];
            a0 += q.x * k0.x + q.y * k0.y + q.z * k0.z + q.w * k0.w;
            a1 += q.x * k1.x + q.y * k1.y + q.z * k1.z + q.w * k1.w;
            a2 += q.x * k2.x + q.y * k2.y + q.z * k2.z + q.w * k2.w;
            a3 += q.x * k3.x + q.y * k3.y + q.z * k3.z + q.w * k3.w;
        }
        const int ih = i / 7, iw = i - ih * 7;
        float av[4] = {a0, a1, a2, a3};
        #pragma unroll
        for (int jj = 0; jj < 4; jj++) {
            const int j = j0 + jj;
            if (j < NTOK) {
                const int jh = j / 7, jw = j - jh * 7;
                const int ridx = (ih - jh + 6) * 13 + (iw - jw + 6);
                ss[i][j] = av[jj] * scale + __ldg(&bias_table[ridx * NHEADS + h])
                         + __ldg(&mrow[i * NTOK + j]);
            }
        }
    }
    __syncthreads();

    // softmax: one warp per row
    const int wid = tid >> 5, lane = tid & 31;
    for (int i = wid; i < NTOK; i += 8) {
        const float v1 = ss[i][lane];
        const float v2 = (lane < 17) ? ss[i][lane + 32] : -1e30f;
        float m = fmaxf(v1, v2);
        #pragma unroll
        for (int o = 16; o > 0; o >>= 1) m = fmaxf(m, __shfl_xor_sync(0xffffffffu, m, o));
        const float e1 = __expf(v1 - m);
        const float e2 = (lane < 17) ? __expf(v2 - m) : 0.f;
        float s = e1 + e2;
        #pragma unroll
        for (int o = 16; o > 0; o >>= 1) s += __shfl_xor_sync(0xffffffffu, s, o);
        const float inv = 1.f / s;
        ss[i][lane] = e1 * inv;
        if (lane < 17) ss[i][lane + 32] = e2 * inv;
    }
    __syncthreads();

    // PV: unit = (i, d-group of 4); 49*8 units; split-write to ctx planes
    const size_t obase = (size_t)bn * NTOK * DIM + h * DHEAD;
    for (int u = tid; u < NTOK * 8; u += 256) {
        const int i  = u >> 3;
        const int d0 = (u & 7) * 4;
        float4 a = make_float4(0.f, 0.f, 0.f, 0.f);
        #pragma unroll 7
        for (int j = 0; j < NTOK; j++) {
            const float pj = ss[i][j];
            const float4 vv = *(const float4*)&sv[j][d0];
            a.x += pj * vv.x; a.y += pj * vv.y; a.z += pj * vv.z; a.w += pj * vv.w;
        }
        uint32_t h01, l01, h23, l23;
        split2(a.x, a.y, h01, l01);
        split2(a.z, a.w, h23, l23);
        const size_t o = obase + (size_t)i * DIM + d0;
        *(uint2*)(ctxH + o) = make_uint2(h01, h23);
        *(uint2*)(ctxL + o) = make_uint2(l01, l23);
    }
}

// ---------------------------------------------------------------------------
extern "C" void kernel_launch(void* const* d_in, const int* in_sizes, int n_in,
                              void* d_out, int out_size)
{
    const float* x          = (const float*)d_in[0];
    const float* mask       = (const float*)d_in[1];
    const float* w_qkv      = (const float*)d_in[2];
    const float* b_qkv      = (const float*)d_in[3];
    const float* w_proj     = (const float*)d_in[4];
    const float* b_proj     = (const float*)d_in[5];
    const float* bias_table = (const float*)d_in[6];
    float* out = (float*)d_out;

    float *qkv = nullptr;
    __half *xH, *xL, *ctxH, *ctxL, *wqH, *wqL, *wpH, *wpL;
    cudaGetSymbolAddress((void**)&qkv,  g_qkv);
    cudaGetSymbolAddress((void**)&xH,   g_xH);
    cudaGetSymbolAddress((void**)&xL,   g_xL);
    cudaGetSymbolAddress((void**)&ctxH, g_ctxH);
    cudaGetSymbolAddress((void**)&ctxL, g_ctxL);
    cudaGetSymbolAddress((void**)&wqH,  g_wqkvH);
    cudaGetSymbolAddress((void**)&wqL,  g_wqkvL);
    cudaGetSymbolAddress((void**)&wpH,  g_wprojH);
    cudaGetSymbolAddress((void**)&wpL,  g_wprojL);

    cudaFuncSetAttribute(gemm_hilo_nt, cudaFuncAttributeMaxDynamicSharedMemorySize, SM_GEMM_TOTAL);

    // 0) split inputs/weights into fp16 hi/lo planes
    split_kernel<<<1184, 256>>>(x, xH, xL, (size_t)TOKENS * DIM / 4);
    split_kernel<<<432, 256>>>(w_qkv, wqH, wqL, (size_t)QKV_COLS * DIM / 4);
    split_kernel<<<144, 256>>>(w_proj, wpH, wpL, (size_t)DIM * DIM / 4);

    // 1) QKV projection
    {
        dim3 grid(QKV_COLS / 128, TOKENS / 128);
        gemm_hilo_nt<<<grid, 256, SM_GEMM_TOTAL>>>(xH, xL, wqH, wqL, b_qkv, qkv,
                                                   TOKENS, QKV_COLS, DIM);
    }
    // 2) fused windowed attention (writes ctx hi/lo planes)
    attn_kernel<<<BN_TOTAL * NHEADS, 256>>>(mask, bias_table, ctxH, ctxL);
    // 3) output projection
    {
        dim3 grid(DIM / 128, TOKENS / 128);
        gemm_hilo_nt<<<grid, 256, SM_GEMM_TOTAL>>>(ctxH, ctxL, wpH, wpL, b_proj, out,
                                                   TOKENS, DIM, DIM);
    }
}

// round 6
// speedup vs baseline: 1.4889x; 1.4889x over previous
#include <cuda_runtime.h>
#include <cuda_fp16.h>
#include <cstdint>
#include <cstddef>

// ---------------------------------------------------------------------------
// Problem constants
// ---------------------------------------------------------------------------
#define NHEADS   12
#define DHEAD    32
#define NTOK     49
#define DIM      384
#define BN_TOTAL 4096
#define TOKENS   (BN_TOTAL * NTOK)   // 200704
#define QKV_COLS 1152

// Scratch (allocation-free rule: device globals)
__device__ float  g_qkv[(size_t)TOKENS * QKV_COLS];   // fp32 qkv for attention
__device__ __half g_xH[(size_t)TOKENS * DIM];
__device__ __half g_xL[(size_t)TOKENS * DIM];
__device__ __half g_ctxH[(size_t)TOKENS * DIM];
__device__ __half g_ctxL[(size_t)TOKENS * DIM];
__device__ __half g_wqkvH[(size_t)QKV_COLS * DIM];
__device__ __half g_wqkvL[(size_t)QKV_COLS * DIM];
__device__ __half g_wprojH[(size_t)DIM * DIM];
__device__ __half g_wprojL[(size_t)DIM * DIM];

// ---------------------------------------------------------------------------
// Common device helpers
// ---------------------------------------------------------------------------
__device__ __forceinline__ void split2(float x, float y, uint32_t& hi, uint32_t& lo) {
    half2 h = __floats2half2_rn(x, y);
    float rx = x - __low2float(h);
    float ry = y - __high2float(h);
    half2 l = __floats2half2_rn(rx, ry);
    hi = *(uint32_t*)&h;
    lo = *(uint32_t*)&l;
}

__device__ __forceinline__ void mma_f16(float* d, const uint32_t* a, const uint32_t* b) {
    asm volatile(
        "mma.sync.aligned.m16n8k16.row.col.f32.f16.f16.f32 "
        "{%0,%1,%2,%3}, {%4,%5,%6,%7}, {%8,%9}, {%0,%1,%2,%3};"
        : "+f"(d[0]), "+f"(d[1]), "+f"(d[2]), "+f"(d[3])
        : "r"(a[0]), "r"(a[1]), "r"(a[2]), "r"(a[3]), "r"(b[0]), "r"(b[1]));
}

__device__ __forceinline__ void ldmx4(uint32_t* r, uint32_t addr) {
    asm volatile("ldmatrix.sync.aligned.m8n8.x4.shared.b16 {%0,%1,%2,%3}, [%4];"
        : "=r"(r[0]), "=r"(r[1]), "=r"(r[2]), "=r"(r[3]) : "r"(addr));
}

__device__ __forceinline__ uint32_t smem_u32(const void* p) {
    uint32_t a;
    asm("{ .reg .u64 t; cvta.to.shared.u64 t, %1; cvt.u32.u64 %0, t; }"
        : "=r"(a) : "l"(p));
    return a;
}

#define CP_ASYNC16(dst, src) \
    asm volatile("cp.async.cg.shared.global [%0], [%1], 16;" :: "r"(dst), "l"(src))
#define CP_COMMIT() asm volatile("cp.async.commit_group;" ::: "memory")
#define CP_WAIT(n)  asm volatile("cp.async.wait_group %0;" :: "n"(n) : "memory")

// ---------------------------------------------------------------------------
// Prep: split fp32 -> fp16 hi/lo planes
// ---------------------------------------------------------------------------
__global__ void split_kernel(const float* __restrict__ src,
                             __half* __restrict__ hi, __half* __restrict__ lo,
                             size_t n4)
{
    const size_t stride = (size_t)gridDim.x * blockDim.x;
    for (size_t i = (size_t)blockIdx.x * blockDim.x + threadIdx.x; i < n4; i += stride) {
        float4 v = *((const float4*)src + i);
        uint32_t h01, l01, h23, l23;
        split2(v.x, v.y, h01, l01);
        split2(v.z, v.w, h23, l23);
        *(uint2*)(hi + i * 4) = make_uint2(h01, h23);
        *(uint2*)(lo + i * 4) = make_uint2(l01, l23);
    }
}

// ---------------------------------------------------------------------------
// fp16 hi/lo GEMM (NT): C = (AH+AL)(BH+BL)^T + bias, 3-term MMA.
// BM=BN=128, BK=16, 3-stage cp.async pipeline, ldmatrix fragments.
// ---------------------------------------------------------------------------
#define GBM 128
#define GBK 16
#define PLANE_BYTES (128 * 24 * 2)        // 6144 (row stride 48B)
#define BUF_BYTES   (4 * PLANE_BYTES)     // 24576
#define NSTAGE 3
#define SM_GEMM_TOTAL (NSTAGE * BUF_BYTES)   // 73728

__global__ __launch_bounds__(256, 2)
void gemm_hilo_nt(const __half* __restrict__ AH, const __half* __restrict__ AL,
                  const __half* __restrict__ BH, const __half* __restrict__ BL,
                  const float* __restrict__ bias, float* __restrict__ C,
                  int M, int N, int K)
{
    extern __shared__ char sm[];
    const uint32_t smb = smem_u32(sm);

    const int tid  = threadIdx.x;
    const int wid  = tid >> 5;
    const int lane = tid & 31;
    const int g = lane >> 2;
    const int c = lane & 3;
    const int wm = wid & 1;
    const int wn = wid >> 1;

    const int m0 = blockIdx.y * GBM;
    const int n0 = blockIdx.x * GBM;

    // staging: thread t: row sr = t>>1, 16B chunk sc2 = t&1 of each plane
    const int sr  = tid >> 1;
    const int sc2 = tid & 1;
    const __half* gA_H = AH + (size_t)(m0 + sr) * K + sc2 * 8;
    const __half* gA_L = AL + (size_t)(m0 + sr) * K + sc2 * 8;
    const __half* gB_H = BH + (size_t)(n0 + sr) * K + sc2 * 8;
    const __half* gB_L = BL + (size_t)(n0 + sr) * K + sc2 * 8;
    const uint32_t dstOff = (uint32_t)sr * 48 + (uint32_t)sc2 * 16;

    // ldmatrix lane addressing
    const int m_idx = lane >> 3;
    const int rin   = lane & 7;
    const uint32_t aRowOff = (uint32_t)(wm * 64 + (m_idx & 1) * 8 + rin) * 48
                           + (uint32_t)(m_idx >> 1) * 16;
    const uint32_t bRowOff = (uint32_t)(wn * 32 + (m_idx >> 1) * 8 + rin) * 48
                           + (uint32_t)(m_idx & 1) * 16;

    float acc[4][4][4];
    #pragma unroll
    for (int i = 0; i < 4; i++)
        #pragma unroll
        for (int j = 0; j < 4; j++)
            #pragma unroll
            for (int r = 0; r < 4; r++) acc[i][j][r] = 0.f;

    const int NK = K / GBK;

    // ---- prologue: stage chunks 0 and 1 ----
    #pragma unroll
    for (int s = 0; s < 2; s++) {
        const uint32_t dst = smb + (uint32_t)s * BUF_BYTES + dstOff;
        const size_t go = (size_t)s * GBK;
        CP_ASYNC16(dst + 0 * PLANE_BYTES, gA_H + go);
        CP_ASYNC16(dst + 1 * PLANE_BYTES, gA_L + go);
        CP_ASYNC16(dst + 2 * PLANE_BYTES, gB_H + go);
        CP_ASYNC16(dst + 3 * PLANE_BYTES, gB_L + go);
        CP_COMMIT();
    }

    int cur = 0, nx2 = 2;   // kt%3 and (kt+2)%3
    for (int kt = 0; kt < NK; kt++) {
        if (kt + 1 < NK) { CP_WAIT(1); } else { CP_WAIT(0); }
        __syncthreads();

        // issue stage kt+2 (after sync: buffer (kt+2)%3 fully consumed)
        if (kt + 2 < NK) {
            const uint32_t dst = smb + (uint32_t)nx2 * BUF_BYTES + dstOff;
            const size_t go = (size_t)(kt + 2) * GBK;
            CP_ASYNC16(dst + 0 * PLANE_BYTES, gA_H + go);
            CP_ASYNC16(dst + 1 * PLANE_BYTES, gA_L + go);
            CP_ASYNC16(dst + 2 * PLANE_BYTES, gB_H + go);
            CP_ASYNC16(dst + 3 * PLANE_BYTES, gB_L + go);
            CP_COMMIT();
        }

        const uint32_t bufB = smb + (uint32_t)cur * BUF_BYTES;

        uint32_t bHf[4][2], bLf[4][2], af[4][4];
        #pragma unroll
        for (int p = 0; p < 2; p++) {
            uint32_t r4[4];
            ldmx4(r4, bufB + 2 * PLANE_BYTES + bRowOff + (uint32_t)p * 16 * 48);
            bHf[2 * p][0] = r4[0]; bHf[2 * p][1] = r4[1];
            bHf[2 * p + 1][0] = r4[2]; bHf[2 * p + 1][1] = r4[3];
            ldmx4(r4, bufB + 3 * PLANE_BYTES + bRowOff + (uint32_t)p * 16 * 48);
            bLf[2 * p][0] = r4[0]; bLf[2 * p][1] = r4[1];
            bLf[2 * p + 1][0] = r4[2]; bLf[2 * p + 1][1] = r4[3];
        }
        #pragma unroll
        for (int tm = 0; tm < 4; tm++)
            ldmx4(af[tm], bufB + 0 * PLANE_BYTES + aRowOff + (uint32_t)tm * 16 * 48);

        #pragma unroll
        for (int tm = 0; tm < 4; tm++)
            #pragma unroll
            for (int tn = 0; tn < 4; tn++) {
                mma_f16(acc[tm][tn], af[tm], bHf[tn]);
                mma_f16(acc[tm][tn], af[tm], bLf[tn]);
            }

        #pragma unroll
        for (int tm = 0; tm < 4; tm++)
            ldmx4(af[tm], bufB + 1 * PLANE_BYTES + aRowOff + (uint32_t)tm * 16 * 48);

        #pragma unroll
        for (int tm = 0; tm < 4; tm++)
            #pragma unroll
            for (int tn = 0; tn < 4; tn++)
                mma_f16(acc[tm][tn], af[tm], bHf[tn]);

        cur = (cur == 2) ? 0 : cur + 1;
        nx2 = (nx2 == 2) ? 0 : nx2 + 1;
    }

    // ---- epilogue: bias + fp32 store ----
    #pragma unroll
    for (int tm = 0; tm < 4; tm++) {
        const int r = m0 + wm * 64 + tm * 16 + g;
        #pragma unroll
        for (int tn = 0; tn < 4; tn++) {
            const int col = n0 + wn * 32 + tn * 8 + 2 * c;
            const float b0 = __ldg(&bias[col]);
            const float b1 = __ldg(&bias[col + 1]);
            float2 o0 = make_float2(acc[tm][tn][0] + b0, acc[tm][tn][1] + b1);
            float2 o1 = make_float2(acc[tm][tn][2] + b0, acc[tm][tn][3] + b1);
            *(float2*)(C + (size_t)r * N + col)       = o0;
            *(float2*)(C + (size_t)(r + 8) * N + col) = o1;
        }
    }
}

// ---------------------------------------------------------------------------
// Fused windowed attention, XOR-swizzled smem, register-tiled units.
// Block = (bn, head), 128 threads. Writes ctx hi/lo fp16 planes.
// ---------------------------------------------------------------------------
// smem: q/k/v as float4[52 rows][9 slots]; slot = kk4 ^ ((row>>2)&7); slot 8 = pad
#define AROW 9
__device__ __forceinline__ int aidx(int row, int kk4) {
    return row * AROW + (kk4 ^ ((row >> 2) & 7));
}

__global__ __launch_bounds__(128) void attn_kernel(
    const float* __restrict__ mask,
    const float* __restrict__ bias_table,
    __half* __restrict__ ctxH, __half* __restrict__ ctxL)
{
    __shared__ float4 sq[52 * AROW];
    __shared__ float4 sk[52 * AROW];
    __shared__ float4 sv[52 * AROW];
    __shared__ float  ss[52 * 52];

    const int b  = blockIdx.x;
    const int bn = b / NHEADS;
    const int h  = b - bn * NHEADS;
    const int tid = threadIdx.x;

    // load q/k/v (head slice) into swizzled smem
    const float* base = g_qkv + (size_t)bn * NTOK * QKV_COLS + h * DHEAD;
    for (int e = tid; e < NTOK * 8; e += 128) {
        const int r = e >> 3, kk4 = e & 7;
        const float* p = base + (size_t)r * QKV_COLS + kk4 * 4;
        const int si = aidx(r, kk4);
        sq[si] = *(const float4*)(p);
        sk[si] = *(const float4*)(p + DIM);
        sv[si] = *(const float4*)(p + 2 * DIM);
    }
    __syncthreads();

    const float scale = 0.17677669529663687f;
    const int win = bn >> 6;
    const float* mrow = mask + (size_t)win * (NTOK * NTOK);

    // ---- QK^T: units of 4i x 4j, 13x13 = 169 units ----
    for (int u = tid; u < 169; u += 128) {
        const int ig = u / 13, jg = u - ig * 13;
        const int i0 = ig * 4, j0 = jg * 4;
        const int qsw = ig & 7, ksw = jg & 7;

        float a[4][4];
        #pragma unroll
        for (int x = 0; x < 4; x++)
            #pragma unroll
            for (int y = 0; y < 4; y++) a[x][y] = 0.f;

        #pragma unroll
        for (int kk4 = 0; kk4 < 8; kk4++) {
            float4 q[4], k[4];
            #pragma unroll
            for (int x = 0; x < 4; x++) q[x] = sq[(i0 + x) * AROW + (kk4 ^ qsw)];
            #pragma unroll
            for (int y = 0; y < 4; y++) k[y] = sk[(j0 + y) * AROW + (kk4 ^ ksw)];
            #pragma unroll
            for (int x = 0; x < 4; x++)
                #pragma unroll
                for (int y = 0; y < 4; y++)
                    a[x][y] += q[x].x * k[y].x + q[x].y * k[y].y
                             + q[x].z * k[y].z + q[x].w * k[y].w;
        }

        #pragma unroll
        for (int x = 0; x < 4; x++) {
            const int i = i0 + x;
            if (i >= NTOK) break;
            const int ih = i / 7, iw = i - ih * 7;
            #pragma unroll
            for (int y = 0; y < 4; y++) {
                const int j = j0 + y;
                if (j < NTOK) {
                    const int jh = j / 7, jw = j - jh * 7;
                    const int ridx = (ih - jh + 6) * 13 + (iw - jw + 6);
                    ss[i * 52 + j] = a[x][y] * scale
                                   + __ldg(&bias_table[ridx * NHEADS + h])
                                   + __ldg(&mrow[i * NTOK + j]);
                }
            }
        }
    }
    __syncthreads();

    // ---- softmax: 4 warps, one row each ----
    const int wid = tid >> 5, lane = tid & 31;
    for (int i = wid; i < NTOK; i += 4) {
        const float v1 = ss[i * 52 + lane];
        const float v2 = (lane < 17) ? ss[i * 52 + lane + 32] : -1e30f;
        float m = fmaxf(v1, v2);
        #pragma unroll
        for (int o = 16; o > 0; o >>= 1) m = fmaxf(m, __shfl_xor_sync(0xffffffffu, m, o));
        const float e1 = __expf(v1 - m);
        const float e2 = (lane < 17) ? __expf(v2 - m) : 0.f;
        float s = e1 + e2;
        #pragma unroll
        for (int o = 16; o > 0; o >>= 1) s += __shfl_xor_sync(0xffffffffu, s, o);
        const float inv = 1.f / s;
        ss[i * 52 + lane] = e1 * inv;
        if (lane < 17) ss[i * 52 + lane + 32] = e2 * inv;
    }
    __syncthreads();

    // ---- PV: units of 4i x 4d, 13x8 = 104 units (single pass) ----
    const size_t obase = (size_t)bn * NTOK * DIM + h * DHEAD;
    if (tid < 104) {
        const int ig = tid >> 3, dg = tid & 7;
        const int i0 = ig * 4;

        float4 acc[4];
        #pragma unroll
        for (int x = 0; x < 4; x++) acc[x] = make_float4(0.f, 0.f, 0.f, 0.f);

        for (int j = 0; j < NTOK; j++) {
            const float4 v = sv[j * AROW + (dg ^ ((j >> 2) & 7))];
            #pragma unroll
            for (int x = 0; x < 4; x++) {
                const float p = ss[(i0 + x) * 52 + j];
                acc[x].x += p * v.x; acc[x].y += p * v.y;
                acc[x].z += p * v.z; acc[x].w += p * v.w;
            }
        }

        #pragma unroll
        for (int x = 0; x < 4; x++) {
            const int i = i0 + x;
            if (i < NTOK) {
                uint32_t h01, l01, h23, l23;
                split2(acc[x].x, acc[x].y, h01, l01);
                split2(acc[x].z, acc[x].w, h23, l23);
                const size_t o = obase + (size_t)i * DIM + dg * 4;
                *(uint2*)(ctxH + o) = make_uint2(h01, h23);
                *(uint2*)(ctxL + o) = make_uint2(l01, l23);
            }
        }
    }
}

// ---------------------------------------------------------------------------
extern "C" void kernel_launch(void* const* d_in, const int* in_sizes, int n_in,
                              void* d_out, int out_size)
{
    const float* x          = (const float*)d_in[0];
    const float* mask       = (const float*)d_in[1];
    const float* w_qkv      = (const float*)d_in[2];
    const float* b_qkv      = (const float*)d_in[3];
    const float* w_proj     = (const float*)d_in[4];
    const float* b_proj     = (const float*)d_in[5];
    const float* bias_table = (const float*)d_in[6];
    float* out = (float*)d_out;

    float *qkv = nullptr;
    __half *xH, *xL, *ctxH, *ctxL, *wqH, *wqL, *wpH, *wpL;
    cudaGetSymbolAddress((void**)&qkv,  g_qkv);
    cudaGetSymbolAddress((void**)&xH,   g_xH);
    cudaGetSymbolAddress((void**)&xL,   g_xL);
    cudaGetSymbolAddress((void**)&ctxH, g_ctxH);
    cudaGetSymbolAddress((void**)&ctxL, g_ctxL);
    cudaGetSymbolAddress((void**)&wqH,  g_wqkvH);
    cudaGetSymbolAddress((void**)&wqL,  g_wqkvL);
    cudaGetSymbolAddress((void**)&wpH,  g_wprojH);
    cudaGetSymbolAddress((void**)&wpL,  g_wprojL);

    cudaFuncSetAttribute(gemm_hilo_nt, cudaFuncAttributeMaxDynamicSharedMemorySize, SM_GEMM_TOTAL);

    // 0) split inputs/weights into fp16 hi/lo planes
    split_kernel<<<1184, 256>>>(x, xH, xL, (size_t)TOKENS * DIM / 4);
    split_kernel<<<432, 256>>>(w_qkv, wqH, wqL, (size_t)QKV_COLS * DIM / 4);
    split_kernel<<<144, 256>>>(w_proj, wpH, wpL, (size_t)DIM * DIM / 4);

    // 1) QKV projection
    {
        dim3 grid(QKV_COLS / 128, TOKENS / 128);
        gemm_hilo_nt<<<grid, 256, SM_GEMM_TOTAL>>>(xH, xL, wqH, wqL, b_qkv, qkv,
                                                   TOKENS, QKV_COLS, DIM);
    }
    // 2) fused windowed attention (writes ctx hi/lo planes)
    attn_kernel<<<BN_TOTAL * NHEADS, 128>>>(mask, bias_table, ctxH, ctxL);
    // 3) output projection
    {
        dim3 grid(DIM / 128, TOKENS / 128);
        gemm_hilo_nt<<<grid, 256, SM_GEMM_TOTAL>>>(ctxH, ctxL, wpH, wpL, b_proj, out,
                                                   TOKENS, DIM, DIM);
    }
}

// round 7
// speedup vs baseline: 1.6189x; 1.0873x over previous
#include <cuda_runtime.h>
#include <cuda_fp16.h>
#include <cstdint>
#include <cstddef>

// ---------------------------------------------------------------------------
// Problem constants
// ---------------------------------------------------------------------------
#define NHEADS   12
#define DHEAD    32
#define NTOK     49
#define DIM      384
#define BN_TOTAL 4096
#define TOKENS   (BN_TOTAL * NTOK)   // 200704
#define QKV_COLS 1152

// Scratch (allocation-free rule: device globals)
__device__ __half g_qkvH[(size_t)TOKENS * QKV_COLS];
__device__ __half g_qkvL[(size_t)TOKENS * QKV_COLS];
__device__ __half g_xH[(size_t)TOKENS * DIM];
__device__ __half g_xL[(size_t)TOKENS * DIM];
__device__ __half g_ctxH[(size_t)TOKENS * DIM];
__device__ __half g_ctxL[(size_t)TOKENS * DIM];
__device__ __half g_wqkvH[(size_t)QKV_COLS * DIM];
__device__ __half g_wqkvL[(size_t)QKV_COLS * DIM];
__device__ __half g_wprojH[(size_t)DIM * DIM];
__device__ __half g_wprojL[(size_t)DIM * DIM];

// ---------------------------------------------------------------------------
// Common device helpers
// ---------------------------------------------------------------------------
__device__ __forceinline__ void split2(float x, float y, uint32_t& hi, uint32_t& lo) {
    half2 h = __floats2half2_rn(x, y);
    float rx = x - __low2float(h);
    float ry = y - __high2float(h);
    half2 l = __floats2half2_rn(rx, ry);
    hi = *(uint32_t*)&h;
    lo = *(uint32_t*)&l;
}

__device__ __forceinline__ void mma_f16(float* d, const uint32_t* a, const uint32_t* b) {
    asm volatile(
        "mma.sync.aligned.m16n8k16.row.col.f32.f16.f16.f32 "
        "{%0,%1,%2,%3}, {%4,%5,%6,%7}, {%8,%9}, {%0,%1,%2,%3};"
        : "+f"(d[0]), "+f"(d[1]), "+f"(d[2]), "+f"(d[3])
        : "r"(a[0]), "r"(a[1]), "r"(a[2]), "r"(a[3]), "r"(b[0]), "r"(b[1]));
}

__device__ __forceinline__ void ldmx4(uint32_t* r, uint32_t addr) {
    asm volatile("ldmatrix.sync.aligned.m8n8.x4.shared.b16 {%0,%1,%2,%3}, [%4];"
        : "=r"(r[0]), "=r"(r[1]), "=r"(r[2]), "=r"(r[3]) : "r"(addr));
}
__device__ __forceinline__ void ldmx4t(uint32_t* r, uint32_t addr) {
    asm volatile("ldmatrix.sync.aligned.m8n8.x4.trans.shared.b16 {%0,%1,%2,%3}, [%4];"
        : "=r"(r[0]), "=r"(r[1]), "=r"(r[2]), "=r"(r[3]) : "r"(addr));
}

__device__ __forceinline__ uint32_t smem_u32(const void* p) {
    uint32_t a;
    asm("{ .reg .u64 t; cvta.to.shared.u64 t, %1; cvt.u32.u64 %0, t; }"
        : "=r"(a) : "l"(p));
    return a;
}

#define CP_ASYNC16(dst, src) \
    asm volatile("cp.async.cg.shared.global [%0], [%1], 16;" :: "r"(dst), "l"(src))
#define CP_COMMIT() asm volatile("cp.async.commit_group;" ::: "memory")
#define CP_WAIT(n)  asm volatile("cp.async.wait_group %0;" :: "n"(n) : "memory")

// ---------------------------------------------------------------------------
// Prep: split fp32 -> fp16 hi/lo planes
// ---------------------------------------------------------------------------
__global__ void split_kernel(const float* __restrict__ src,
                             __half* __restrict__ hi, __half* __restrict__ lo,
                             size_t n4)
{
    const size_t stride = (size_t)gridDim.x * blockDim.x;
    for (size_t i = (size_t)blockIdx.x * blockDim.x + threadIdx.x; i < n4; i += stride) {
        float4 v = *((const float4*)src + i);
        uint32_t h01, l01, h23, l23;
        split2(v.x, v.y, h01, l01);
        split2(v.z, v.w, h23, l23);
        *(uint2*)(hi + i * 4) = make_uint2(h01, h23);
        *(uint2*)(lo + i * 4) = make_uint2(l01, l23);
    }
}

// ---------------------------------------------------------------------------
// fp16 hi/lo GEMM (NT): C = (AH+AL)(BH+BL)^T + bias, 3-term MMA.
// BM=BN=128, BK=16, 3-stage cp.async pipeline, ldmatrix fragments.
// outHalf: 1 -> write CH/CL fp16 planes; 0 -> write Cf fp32.
// ---------------------------------------------------------------------------
#define GBM 128
#define GBK 16
#define PLANE_BYTES (128 * 24 * 2)        // 6144 (row stride 48B)
#define BUF_BYTES   (4 * PLANE_BYTES)     // 24576
#define NSTAGE 3
#define SM_GEMM_TOTAL (NSTAGE * BUF_BYTES)   // 73728

__global__ __launch_bounds__(256, 2)
void gemm_hilo_nt(const __half* __restrict__ AH, const __half* __restrict__ AL,
                  const __half* __restrict__ BH, const __half* __restrict__ BL,
                  const float* __restrict__ bias,
                  float* __restrict__ Cf,
                  __half* __restrict__ CH, __half* __restrict__ CL,
                  int M, int N, int K, int outHalf)
{
    extern __shared__ char sm[];
    const uint32_t smb = smem_u32(sm);

    const int tid  = threadIdx.x;
    const int wid  = tid >> 5;
    const int lane = tid & 31;
    const int g = lane >> 2;
    const int c = lane & 3;
    const int wm = wid & 1;
    const int wn = wid >> 1;

    const int m0 = blockIdx.y * GBM;
    const int n0 = blockIdx.x * GBM;

    const int sr  = tid >> 1;
    const int sc2 = tid & 1;
    const __half* gA_H = AH + (size_t)(m0 + sr) * K + sc2 * 8;
    const __half* gA_L = AL + (size_t)(m0 + sr) * K + sc2 * 8;
    const __half* gB_H = BH + (size_t)(n0 + sr) * K + sc2 * 8;
    const __half* gB_L = BL + (size_t)(n0 + sr) * K + sc2 * 8;
    const uint32_t dstOff = (uint32_t)sr * 48 + (uint32_t)sc2 * 16;

    const int m_idx = lane >> 3;
    const int rin   = lane & 7;
    const uint32_t aRowOff = (uint32_t)(wm * 64 + (m_idx & 1) * 8 + rin) * 48
                           + (uint32_t)(m_idx >> 1) * 16;
    const uint32_t bRowOff = (uint32_t)(wn * 32 + (m_idx >> 1) * 8 + rin) * 48
                           + (uint32_t)(m_idx & 1) * 16;

    float acc[4][4][4];
    #pragma unroll
    for (int i = 0; i < 4; i++)
        #pragma unroll
        for (int j = 0; j < 4; j++)
            #pragma unroll
            for (int r = 0; r < 4; r++) acc[i][j][r] = 0.f;

    const int NK = K / GBK;

    #pragma unroll
    for (int s = 0; s < 2; s++) {
        const uint32_t dst = smb + (uint32_t)s * BUF_BYTES + dstOff;
        const size_t go = (size_t)s * GBK;
        CP_ASYNC16(dst + 0 * PLANE_BYTES, gA_H + go);
        CP_ASYNC16(dst + 1 * PLANE_BYTES, gA_L + go);
        CP_ASYNC16(dst + 2 * PLANE_BYTES, gB_H + go);
        CP_ASYNC16(dst + 3 * PLANE_BYTES, gB_L + go);
        CP_COMMIT();
    }

    int cur = 0, nx2 = 2;
    for (int kt = 0; kt < NK; kt++) {
        if (kt + 1 < NK) { CP_WAIT(1); } else { CP_WAIT(0); }
        __syncthreads();

        if (kt + 2 < NK) {
            const uint32_t dst = smb + (uint32_t)nx2 * BUF_BYTES + dstOff;
            const size_t go = (size_t)(kt + 2) * GBK;
            CP_ASYNC16(dst + 0 * PLANE_BYTES, gA_H + go);
            CP_ASYNC16(dst + 1 * PLANE_BYTES, gA_L + go);
            CP_ASYNC16(dst + 2 * PLANE_BYTES, gB_H + go);
            CP_ASYNC16(dst + 3 * PLANE_BYTES, gB_L + go);
            CP_COMMIT();
        }

        const uint32_t bufB = smb + (uint32_t)cur * BUF_BYTES;

        uint32_t bHf[4][2], bLf[4][2], af[4][4];
        #pragma unroll
        for (int p = 0; p < 2; p++) {
            uint32_t r4[4];
            ldmx4(r4, bufB + 2 * PLANE_BYTES + bRowOff + (uint32_t)p * 16 * 48);
            bHf[2 * p][0] = r4[0]; bHf[2 * p][1] = r4[1];
            bHf[2 * p + 1][0] = r4[2]; bHf[2 * p + 1][1] = r4[3];
            ldmx4(r4, bufB + 3 * PLANE_BYTES + bRowOff + (uint32_t)p * 16 * 48);
            bLf[2 * p][0] = r4[0]; bLf[2 * p][1] = r4[1];
            bLf[2 * p + 1][0] = r4[2]; bLf[2 * p + 1][1] = r4[3];
        }
        #pragma unroll
        for (int tm = 0; tm < 4; tm++)
            ldmx4(af[tm], bufB + 0 * PLANE_BYTES + aRowOff + (uint32_t)tm * 16 * 48);

        #pragma unroll
        for (int tm = 0; tm < 4; tm++)
            #pragma unroll
            for (int tn = 0; tn < 4; tn++) {
                mma_f16(acc[tm][tn], af[tm], bHf[tn]);
                mma_f16(acc[tm][tn], af[tm], bLf[tn]);
            }

        #pragma unroll
        for (int tm = 0; tm < 4; tm++)
            ldmx4(af[tm], bufB + 1 * PLANE_BYTES + aRowOff + (uint32_t)tm * 16 * 48);

        #pragma unroll
        for (int tm = 0; tm < 4; tm++)
            #pragma unroll
            for (int tn = 0; tn < 4; tn++)
                mma_f16(acc[tm][tn], af[tm], bHf[tn]);

        cur = (cur == 2) ? 0 : cur + 1;
        nx2 = (nx2 == 2) ? 0 : nx2 + 1;
    }

    // ---- epilogue ----
    #pragma unroll
    for (int tm = 0; tm < 4; tm++) {
        const int r = m0 + wm * 64 + tm * 16 + g;
        #pragma unroll
        for (int tn = 0; tn < 4; tn++) {
            const int col = n0 + wn * 32 + tn * 8 + 2 * c;
            const float b0 = __ldg(&bias[col]);
            const float b1 = __ldg(&bias[col + 1]);
            const float o00 = acc[tm][tn][0] + b0, o01 = acc[tm][tn][1] + b1;
            const float o10 = acc[tm][tn][2] + b0, o11 = acc[tm][tn][3] + b1;
            if (outHalf) {
                uint32_t hi, lo;
                split2(o00, o01, hi, lo);
                *(uint32_t*)(CH + (size_t)r * N + col) = hi;
                *(uint32_t*)(CL + (size_t)r * N + col) = lo;
                split2(o10, o11, hi, lo);
                *(uint32_t*)(CH + (size_t)(r + 8) * N + col) = hi;
                *(uint32_t*)(CL + (size_t)(r + 8) * N + col) = lo;
            } else {
                *(float2*)(Cf + (size_t)r * N + col)       = make_float2(o00, o01);
                *(float2*)(Cf + (size_t)(r + 8) * N + col) = make_float2(o10, o11);
            }
        }
    }
}

// ---------------------------------------------------------------------------
// Tensor-core windowed attention. Block = (bn, head), 128 threads / 4 warps.
// Warp w owns score rows 16w..16w+15. 3-term hi/lo MMA for QK^T and PV.
// ---------------------------------------------------------------------------
#define VPITCH 40    // halves per row for Q/K/V planes (80B, LDSM conflict-free)
#define PPITCH 72    // halves per row for P planes (144B, conflict-free)
// smem layout in halves:
#define OFF_QH 0
#define OFF_QL 2560
#define OFF_KH 5120
#define OFF_KL 7680
#define OFF_VH 10240
#define OFF_VL 12800
#define OFF_PH 15360
#define OFF_PL 19968
#define SMEM_HALVES 24576
#define SM_ATTN_TOTAL (SMEM_HALVES * 2)   // 49152 bytes

__global__ __launch_bounds__(128)
void attn_mma(const __half* __restrict__ qkvH, const __half* __restrict__ qkvL,
              const float* __restrict__ mask, const float* __restrict__ bias_table,
              __half* __restrict__ ctxH, __half* __restrict__ ctxL)
{
    extern __shared__ __half sh[];
    const uint32_t smb = smem_u32(sh);

    const int b   = blockIdx.x;
    const int bn  = b / NHEADS;
    const int h   = b - bn * NHEADS;
    const int tid = threadIdx.x;
    const int w    = tid >> 5;
    const int lane = tid & 31;
    const int g    = lane >> 2;
    const int cq   = lane & 3;
    const int m_idx = lane >> 3;
    const int rin   = lane & 7;

    // zero all smem (pads must be 0; avoids NaN paths)
    for (int i = tid; i < SMEM_HALVES / 8; i += 128)
        *(uint4*)(sh + (size_t)i * 8) = make_uint4(0u, 0u, 0u, 0u);
    __syncthreads();

    // cp.async load q/k/v hi+lo head slices: 49 rows x 32 halves x 3 x 2 planes
    {
        const size_t rowbase = (size_t)bn * NTOK * QKV_COLS + (size_t)h * DHEAD;
        for (int e = tid; e < 1176; e += 128) {
            const int c4 = e & 3;
            const int t  = e >> 2;        // 0..293
            const int r  = t % NTOK;
            const int tp = t / NTOK;      // 0..5
            const int pl = tp & 1, t3 = tp >> 1;
            const __half* src = (pl ? qkvL : qkvH) + rowbase + (size_t)r * QKV_COLS
                              + t3 * DIM + c4 * 8;
            const uint32_t dst = smb + (uint32_t)((t3 * 5120 + pl * 2560
                              + r * VPITCH + c4 * 8) * 2);
            CP_ASYNC16(dst, src);
        }
        CP_COMMIT();
        CP_WAIT(0);
    }
    __syncthreads();

    // ---- QK^T: acc[nt][4], nt = score-col tile (8 cols each), rows 16w.. ----
    float acc[7][4];
    #pragma unroll
    for (int nt = 0; nt < 7; nt++)
        #pragma unroll
        for (int r = 0; r < 4; r++) acc[nt][r] = 0.f;

    uint32_t qh[2][4], ql[2][4];
    #pragma unroll
    for (int kt = 0; kt < 2; kt++) {
        const uint32_t a = smb + 2u * (uint32_t)((16 * w + (m_idx & 1) * 8 + rin) * VPITCH
                         + (m_idx >> 1) * 8 + kt * 16);
        ldmx4(qh[kt], a + 2u * OFF_QH);
        ldmx4(ql[kt], a + 2u * OFF_QL);
    }

    uint32_t kf[2][4][4];
    // Kh: terms Qh*Kh + Ql*Kh
    #pragma unroll
    for (int kt = 0; kt < 2; kt++)
        #pragma unroll
        for (int p = 0; p < 4; p++) {
            const uint32_t a = smb + 2u * (uint32_t)(OFF_KH
                             + (16 * p + (m_idx >> 1) * 8 + rin) * VPITCH
                             + (m_idx & 1) * 8 + kt * 16);
            ldmx4(kf[kt][p], a);
        }
    #pragma unroll
    for (int kt = 0; kt < 2; kt++)
        #pragma unroll
        for (int p = 0; p < 4; p++) {
            uint32_t b0[2] = { kf[kt][p][0], kf[kt][p][1] };
            uint32_t b1[2] = { kf[kt][p][2], kf[kt][p][3] };
            mma_f16(acc[2 * p], qh[kt], b0);
            mma_f16(acc[2 * p], ql[kt], b0);
            if (p < 3) {
                mma_f16(acc[2 * p + 1], qh[kt], b1);
                mma_f16(acc[2 * p + 1], ql[kt], b1);
            }
        }
    // Kl: term Qh*Kl
    #pragma unroll
    for (int kt = 0; kt < 2; kt++)
        #pragma unroll
        for (int p = 0; p < 4; p++) {
            const uint32_t a = smb + 2u * (uint32_t)(OFF_KL
                             + (16 * p + (m_idx >> 1) * 8 + rin) * VPITCH
                             + (m_idx & 1) * 8 + kt * 16);
            ldmx4(kf[kt][p], a);
        }
    #pragma unroll
    for (int kt = 0; kt < 2; kt++)
        #pragma unroll
        for (int p = 0; p < 4; p++) {
            uint32_t b0[2] = { kf[kt][p][0], kf[kt][p][1] };
            uint32_t b1[2] = { kf[kt][p][2], kf[kt][p][3] };
            mma_f16(acc[2 * p], qh[kt], b0);
            if (p < 3) mma_f16(acc[2 * p + 1], qh[kt], b1);
        }

    // ---- softmax in fragments ----
    const float scale = 0.17677669529663687f;
    const float* mrow = mask + (size_t)(bn >> 6) * (NTOK * NTOK);
    const int i0 = 16 * w + g, i1 = i0 + 8;

    float sv[7][4];
    float m0 = -1e30f, m1 = -1e30f;
    #pragma unroll
    for (int nt = 0; nt < 7; nt++) {
        #pragma unroll
        for (int r = 0; r < 4; r++) {
            const int i = (r < 2) ? i0 : i1;
            const int j = 8 * nt + 2 * cq + (r & 1);
            float s;
            if (i >= NTOK) s = 0.f;
            else if (j >= NTOK) s = -1e30f;
            else {
                const int ih = i / 7, iw = i - ih * 7;
                const int jh = j / 7, jw = j - jh * 7;
                const int ridx = (ih - jh + 6) * 13 + (iw - jw + 6);
                s = acc[nt][r] * scale + __ldg(&bias_table[ridx * NHEADS + h])
                  + __ldg(&mrow[i * NTOK + j]);
            }
            sv[nt][r] = s;
            if (r < 2) m0 = fmaxf(m0, s); else m1 = fmaxf(m1, s);
        }
    }
    m0 = fmaxf(m0, __shfl_xor_sync(0xffffffffu, m0, 1));
    m0 = fmaxf(m0, __shfl_xor_sync(0xffffffffu, m0, 2));
    m1 = fmaxf(m1, __shfl_xor_sync(0xffffffffu, m1, 1));
    m1 = fmaxf(m1, __shfl_xor_sync(0xffffffffu, m1, 2));

    float s0 = 0.f, s1 = 0.f;
    #pragma unroll
    for (int nt = 0; nt < 7; nt++) {
        #pragma unroll
        for (int r = 0; r < 4; r++) {
            const int i = (r < 2) ? i0 : i1;
            const int j = 8 * nt + 2 * cq + (r & 1);
            const float e = __expf(sv[nt][r] - ((r < 2) ? m0 : m1));
            if (r < 2) s0 += e; else s1 += e;
            const __half eh = __float2half_rn(e);
            const float  el = e - __half2float(eh);
            sh[OFF_PH + i * PPITCH + j] = eh;
            sh[OFF_PL + i * PPITCH + j] = __float2half_rn(el);
        }
    }
    s0 += __shfl_xor_sync(0xffffffffu, s0, 1);
    s0 += __shfl_xor_sync(0xffffffffu, s0, 2);
    s1 += __shfl_xor_sync(0xffffffffu, s1, 1);
    s1 += __shfl_xor_sync(0xffffffffu, s1, 2);
    const float inv0 = 1.f / s0;
    const float inv1 = 1.f / s1;

    __syncwarp();

    // ---- PV: out[i][d] = sum_j P[i][j] V[j][d] ----
    float pv[4][4];
    #pragma unroll
    for (int nt = 0; nt < 4; nt++)
        #pragma unroll
        for (int r = 0; r < 4; r++) pv[nt][r] = 0.f;

    uint32_t pf[4][4];   // P A-frags (4 k-tiles over j)
    uint32_t vf[4][2][4]; // V B-frags via ldmatrix.trans: [ktile][dpair][4]

    const uint32_t pARow = (uint32_t)((16 * w + (m_idx & 1) * 8 + rin) * PPITCH
                         + (m_idx >> 1) * 8);
    // Ph x Vh
    #pragma unroll
    for (int kt = 0; kt < 4; kt++)
        ldmx4(pf[kt], smb + 2u * (uint32_t)(OFF_PH + pARow + kt * 16));
    #pragma unroll
    for (int kt = 0; kt < 4; kt++)
        #pragma unroll
        for (int dp = 0; dp < 2; dp++) {
            const uint32_t a = smb + 2u * (uint32_t)(OFF_VH
                             + (16 * kt + (m_idx & 1) * 8 + rin) * VPITCH
                             + (m_idx >> 1) * 8 + dp * 16);
            ldmx4t(vf[kt][dp], a);
        }
    #pragma unroll
    for (int kt = 0; kt < 4; kt++)
        #pragma unroll
        for (int dp = 0; dp < 2; dp++) {
            uint32_t b0[2] = { vf[kt][dp][0], vf[kt][dp][1] };
            uint32_t b1[2] = { vf[kt][dp][2], vf[kt][dp][3] };
            mma_f16(pv[2 * dp], pf[kt], b0);
            mma_f16(pv[2 * dp + 1], pf[kt], b1);
        }
    // Pl x Vh
    #pragma unroll
    for (int kt = 0; kt < 4; kt++)
        ldmx4(pf[kt], smb + 2u * (uint32_t)(OFF_PL + pARow + kt * 16));
    #pragma unroll
    for (int kt = 0; kt < 4; kt++)
        #pragma unroll
        for (int dp = 0; dp < 2; dp++) {
            uint32_t b0[2] = { vf[kt][dp][0], vf[kt][dp][1] };
            uint32_t b1[2] = { vf[kt][dp][2], vf[kt][dp][3] };
            mma_f16(pv[2 * dp], pf[kt], b0);
            mma_f16(pv[2 * dp + 1], pf[kt], b1);
        }
    // Ph x Vl
    #pragma unroll
    for (int kt = 0; kt < 4; kt++)
        ldmx4(pf[kt], smb + 2u * (uint32_t)(OFF_PH + pARow + kt * 16));
    #pragma unroll
    for (int kt = 0; kt < 4; kt++)
        #pragma unroll
        for (int dp = 0; dp < 2; dp++) {
            const uint32_t a = smb + 2u * (uint32_t)(OFF_VL
                             + (16 * kt + (m_idx & 1) * 8 + rin) * VPITCH
                             + (m_idx >> 1) * 8 + dp * 16);
            ldmx4t(vf[kt][dp], a);
        }
    #pragma unroll
    for (int kt = 0; kt < 4; kt++)
        #pragma unroll
        for (int dp = 0; dp < 2; dp++) {
            uint32_t b0[2] = { vf[kt][dp][0], vf[kt][dp][1] };
            uint32_t b1[2] = { vf[kt][dp][2], vf[kt][dp][3] };
            mma_f16(pv[2 * dp], pf[kt], b0);
            mma_f16(pv[2 * dp + 1], pf[kt], b1);
        }

    // ---- epilogue: normalize, split, store ctx hi/lo ----
    const size_t ob = (size_t)bn * NTOK * DIM + (size_t)h * DHEAD;
    if (i0 < NTOK) {
        #pragma unroll
        for (int nt = 0; nt < 4; nt++) {
            const int d = 8 * nt + 2 * cq;
            uint32_t hi, lo;
            split2(pv[nt][0] * inv0, pv[nt][1] * inv0, hi, lo);
            *(uint32_t*)(ctxH + ob + (size_t)i0 * DIM + d) = hi;
            *(uint32_t*)(ctxL + ob + (size_t)i0 * DIM + d) = lo;
        }
    }
    if (i1 < NTOK) {
        #pragma unroll
        for (int nt = 0; nt < 4; nt++) {
            const int d = 8 * nt + 2 * cq;
            uint32_t hi, lo;
            split2(pv[nt][2] * inv1, pv[nt][3] * inv1, hi, lo);
            *(uint32_t*)(ctxH + ob + (size_t)i1 * DIM + d) = hi;
            *(uint32_t*)(ctxL + ob + (size_t)i1 * DIM + d) = lo;
        }
    }
}

// ---------------------------------------------------------------------------
extern "C" void kernel_launch(void* const* d_in, const int* in_sizes, int n_in,
                              void* d_out, int out_size)
{
    const float* x          = (const float*)d_in[0];
    const float* mask       = (const float*)d_in[1];
    const float* w_qkv      = (const float*)d_in[2];
    const float* b_qkv      = (const float*)d_in[3];
    const float* w_proj     = (const float*)d_in[4];
    const float* b_proj     = (const float*)d_in[5];
    const float* bias_table = (const float*)d_in[6];
    float* out = (float*)d_out;

    __half *qkvH, *qkvL, *xH, *xL, *ctxH, *ctxL, *wqH, *wqL, *wpH, *wpL;
    cudaGetSymbolAddress((void**)&qkvH, g_qkvH);
    cudaGetSymbolAddress((void**)&qkvL, g_qkvL);
    cudaGetSymbolAddress((void**)&xH,   g_xH);
    cudaGetSymbolAddress((void**)&xL,   g_xL);
    cudaGetSymbolAddress((void**)&ctxH, g_ctxH);
    cudaGetSymbolAddress((void**)&ctxL, g_ctxL);
    cudaGetSymbolAddress((void**)&wqH,  g_wqkvH);
    cudaGetSymbolAddress((void**)&wqL,  g_wqkvL);
    cudaGetSymbolAddress((void**)&wpH,  g_wprojH);
    cudaGetSymbolAddress((void**)&wpL,  g_wprojL);

    cudaFuncSetAttribute(gemm_hilo_nt, cudaFuncAttributeMaxDynamicSharedMemorySize, SM_GEMM_TOTAL);
    cudaFuncSetAttribute(attn_mma, cudaFuncAttributeMaxDynamicSharedMemorySize, SM_ATTN_TOTAL);

    // 0) split inputs/weights into fp16 hi/lo planes
    split_kernel<<<1184, 256>>>(x, xH, xL, (size_t)TOKENS * DIM / 4);
    split_kernel<<<432, 256>>>(w_qkv, wqH, wqL, (size_t)QKV_COLS * DIM / 4);
    split_kernel<<<144, 256>>>(w_proj, wpH, wpL, (size_t)DIM * DIM / 4);

    // 1) QKV projection -> fp16 hi/lo planes
    {
        dim3 grid(QKV_COLS / 128, TOKENS / 128);
        gemm_hilo_nt<<<grid, 256, SM_GEMM_TOTAL>>>(xH, xL, wqH, wqL, b_qkv,
                                                   nullptr, qkvH, qkvL,
                                                   TOKENS, QKV_COLS, DIM, 1);
    }
    // 2) tensor-core windowed attention -> ctx hi/lo planes
    attn_mma<<<BN_TOTAL * NHEADS, 128, SM_ATTN_TOTAL>>>(qkvH, qkvL, mask, bias_table,
                                                        ctxH, ctxL);
    // 3) output projection -> fp32 out
    {
        dim3 grid(DIM / 128, TOKENS / 128);
        gemm_hilo_nt<<<grid, 256, SM_GEMM_TOTAL>>>(ctxH, ctxL, wpH, wpL, b_proj,
                                                   out, nullptr, nullptr,
                                                   TOKENS, DIM, DIM, 0);
    }
}

// round 8
// speedup vs baseline: 1.7379x; 1.0735x over previous
#include <cuda_runtime.h>
#include <cuda_fp16.h>
#include <cstdint>
#include <cstddef>

// ---------------------------------------------------------------------------
// Problem constants
// ---------------------------------------------------------------------------
#define NHEADS   12
#define DHEAD    32
#define NTOK     49
#define DIM      384
#define BN_TOTAL 4096
#define TOKENS   (BN_TOTAL * NTOK)   // 200704
#define QKV_COLS 1152

// Scratch (allocation-free rule: device globals)
// qkv planes stored head-blocked: [(comp*12+head)][token][32]
__device__ __half g_qkvH[(size_t)TOKENS * QKV_COLS];
__device__ __half g_qkvL[(size_t)TOKENS * QKV_COLS];
__device__ __half g_xH[(size_t)TOKENS * DIM];
__device__ __half g_xL[(size_t)TOKENS * DIM];
__device__ __half g_ctxH[(size_t)TOKENS * DIM];
__device__ __half g_ctxL[(size_t)TOKENS * DIM];
__device__ __half g_wqkvH[(size_t)QKV_COLS * DIM];
__device__ __half g_wqkvL[(size_t)QKV_COLS * DIM];
__device__ __half g_wprojH[(size_t)DIM * DIM];
__device__ __half g_wprojL[(size_t)DIM * DIM];

// ---------------------------------------------------------------------------
// Common device helpers
// ---------------------------------------------------------------------------
__device__ __forceinline__ void split2(float x, float y, uint32_t& hi, uint32_t& lo) {
    half2 h = __floats2half2_rn(x, y);
    float rx = x - __low2float(h);
    float ry = y - __high2float(h);
    half2 l = __floats2half2_rn(rx, ry);
    hi = *(uint32_t*)&h;
    lo = *(uint32_t*)&l;
}

__device__ __forceinline__ void mma_f16(float* d, const uint32_t* a, const uint32_t* b) {
    asm volatile(
        "mma.sync.aligned.m16n8k16.row.col.f32.f16.f16.f32 "
        "{%0,%1,%2,%3}, {%4,%5,%6,%7}, {%8,%9}, {%0,%1,%2,%3};"
        : "+f"(d[0]), "+f"(d[1]), "+f"(d[2]), "+f"(d[3])
        : "r"(a[0]), "r"(a[1]), "r"(a[2]), "r"(a[3]), "r"(b[0]), "r"(b[1]));
}

__device__ __forceinline__ void ldmx4(uint32_t* r, uint32_t addr) {
    asm volatile("ldmatrix.sync.aligned.m8n8.x4.shared.b16 {%0,%1,%2,%3}, [%4];"
        : "=r"(r[0]), "=r"(r[1]), "=r"(r[2]), "=r"(r[3]) : "r"(addr));
}
__device__ __forceinline__ void ldmx4t(uint32_t* r, uint32_t addr) {
    asm volatile("ldmatrix.sync.aligned.m8n8.x4.trans.shared.b16 {%0,%1,%2,%3}, [%4];"
        : "=r"(r[0]), "=r"(r[1]), "=r"(r[2]), "=r"(r[3]) : "r"(addr));
}

__device__ __forceinline__ uint32_t smem_u32(const void* p) {
    uint32_t a;
    asm("{ .reg .u64 t; cvta.to.shared.u64 t, %1; cvt.u32.u64 %0, t; }"
        : "=r"(a) : "l"(p));
    return a;
}

#define CP_ASYNC16(dst, src) \
    asm volatile("cp.async.cg.shared.global [%0], [%1], 16;" :: "r"(dst), "l"(src))
#define CP_COMMIT() asm volatile("cp.async.commit_group;" ::: "memory")
#define CP_WAIT(n)  asm volatile("cp.async.wait_group %0;" :: "n"(n) : "memory")

// ---------------------------------------------------------------------------
// Prep: split fp32 -> fp16 hi/lo planes
// ---------------------------------------------------------------------------
__global__ void split_kernel(const float* __restrict__ src,
                             __half* __restrict__ hi, __half* __restrict__ lo,
                             size_t n4)
{
    const size_t stride = (size_t)gridDim.x * blockDim.x;
    for (size_t i = (size_t)blockIdx.x * blockDim.x + threadIdx.x; i < n4; i += stride) {
        float4 v = *((const float4*)src + i);
        uint32_t h01, l01, h23, l23;
        split2(v.x, v.y, h01, l01);
        split2(v.z, v.w, h23, l23);
        *(uint2*)(hi + i * 4) = make_uint2(h01, h23);
        *(uint2*)(lo + i * 4) = make_uint2(l01, l23);
    }
}

// ---------------------------------------------------------------------------
// fp16 hi/lo GEMM (NT): C = (AH+AL)(BH+BL)^T + bias, 3-term MMA.
// BM=BN=128, BK=16, 3-stage cp.async pipeline, ldmatrix fragments.
// outHalf=1 -> write CH/CL fp16 planes in HEAD-BLOCKED layout
//              [(col>>5)][row][col&31]; 0 -> write Cf fp32 row-major.
// ---------------------------------------------------------------------------
#define GBM 128
#define GBK 16
#define PLANE_BYTES (128 * 24 * 2)        // 6144 (row stride 48B)
#define BUF_BYTES   (4 * PLANE_BYTES)     // 24576
#define NSTAGE 3
#define SM_GEMM_TOTAL (NSTAGE * BUF_BYTES)   // 73728

__global__ __launch_bounds__(256, 2)
void gemm_hilo_nt(const __half* __restrict__ AH, const __half* __restrict__ AL,
                  const __half* __restrict__ BH, const __half* __restrict__ BL,
                  const float* __restrict__ bias,
                  float* __restrict__ Cf,
                  __half* __restrict__ CH, __half* __restrict__ CL,
                  int M, int N, int K, int outHalf)
{
    extern __shared__ char sm[];
    const uint32_t smb = smem_u32(sm);

    const int tid  = threadIdx.x;
    const int wid  = tid >> 5;
    const int lane = tid & 31;
    const int g = lane >> 2;
    const int c = lane & 3;
    const int wm = wid & 1;
    const int wn = wid >> 1;

    const int m0 = blockIdx.y * GBM;
    const int n0 = blockIdx.x * GBM;

    const int sr  = tid >> 1;
    const int sc2 = tid & 1;
    const __half* gA_H = AH + (size_t)(m0 + sr) * K + sc2 * 8;
    const __half* gA_L = AL + (size_t)(m0 + sr) * K + sc2 * 8;
    const __half* gB_H = BH + (size_t)(n0 + sr) * K + sc2 * 8;
    const __half* gB_L = BL + (size_t)(n0 + sr) * K + sc2 * 8;
    const uint32_t dstOff = (uint32_t)sr * 48 + (uint32_t)sc2 * 16;

    const int m_idx = lane >> 3;
    const int rin   = lane & 7;
    const uint32_t aRowOff = (uint32_t)(wm * 64 + (m_idx & 1) * 8 + rin) * 48
                           + (uint32_t)(m_idx >> 1) * 16;
    const uint32_t bRowOff = (uint32_t)(wn * 32 + (m_idx >> 1) * 8 + rin) * 48
                           + (uint32_t)(m_idx & 1) * 16;

    float acc[4][4][4];
    #pragma unroll
    for (int i = 0; i < 4; i++)
        #pragma unroll
        for (int j = 0; j < 4; j++)
            #pragma unroll
            for (int r = 0; r < 4; r++) acc[i][j][r] = 0.f;

    const int NK = K / GBK;

    #pragma unroll
    for (int s = 0; s < 2; s++) {
        const uint32_t dst = smb + (uint32_t)s * BUF_BYTES + dstOff;
        const size_t go = (size_t)s * GBK;
        CP_ASYNC16(dst + 0 * PLANE_BYTES, gA_H + go);
        CP_ASYNC16(dst + 1 * PLANE_BYTES, gA_L + go);
        CP_ASYNC16(dst + 2 * PLANE_BYTES, gB_H + go);
        CP_ASYNC16(dst + 3 * PLANE_BYTES, gB_L + go);
        CP_COMMIT();
    }

    int cur = 0, nx2 = 2;
    for (int kt = 0; kt < NK; kt++) {
        if (kt + 1 < NK) { CP_WAIT(1); } else { CP_WAIT(0); }
        __syncthreads();

        if (kt + 2 < NK) {
            const uint32_t dst = smb + (uint32_t)nx2 * BUF_BYTES + dstOff;
            const size_t go = (size_t)(kt + 2) * GBK;
            CP_ASYNC16(dst + 0 * PLANE_BYTES, gA_H + go);
            CP_ASYNC16(dst + 1 * PLANE_BYTES, gA_L + go);
            CP_ASYNC16(dst + 2 * PLANE_BYTES, gB_H + go);
            CP_ASYNC16(dst + 3 * PLANE_BYTES, gB_L + go);
            CP_COMMIT();
        }

        const uint32_t bufB = smb + (uint32_t)cur * BUF_BYTES;

        uint32_t bHf[4][2], bLf[4][2], af[4][4];
        #pragma unroll
        for (int p = 0; p < 2; p++) {
            uint32_t r4[4];
            ldmx4(r4, bufB + 2 * PLANE_BYTES + bRowOff + (uint32_t)p * 16 * 48);
            bHf[2 * p][0] = r4[0]; bHf[2 * p][1] = r4[1];
            bHf[2 * p + 1][0] = r4[2]; bHf[2 * p + 1][1] = r4[3];
            ldmx4(r4, bufB + 3 * PLANE_BYTES + bRowOff + (uint32_t)p * 16 * 48);
            bLf[2 * p][0] = r4[0]; bLf[2 * p][1] = r4[1];
            bLf[2 * p + 1][0] = r4[2]; bLf[2 * p + 1][1] = r4[3];
        }
        #pragma unroll
        for (int tm = 0; tm < 4; tm++)
            ldmx4(af[tm], bufB + 0 * PLANE_BYTES + aRowOff + (uint32_t)tm * 16 * 48);

        #pragma unroll
        for (int tm = 0; tm < 4; tm++)
            #pragma unroll
            for (int tn = 0; tn < 4; tn++) {
                mma_f16(acc[tm][tn], af[tm], bHf[tn]);
                mma_f16(acc[tm][tn], af[tm], bLf[tn]);
            }

        #pragma unroll
        for (int tm = 0; tm < 4; tm++)
            ldmx4(af[tm], bufB + 1 * PLANE_BYTES + aRowOff + (uint32_t)tm * 16 * 48);

        #pragma unroll
        for (int tm = 0; tm < 4; tm++)
            #pragma unroll
            for (int tn = 0; tn < 4; tn++)
                mma_f16(acc[tm][tn], af[tm], bHf[tn]);

        cur = (cur == 2) ? 0 : cur + 1;
        nx2 = (nx2 == 2) ? 0 : nx2 + 1;
    }

    // ---- epilogue ----
    #pragma unroll
    for (int tm = 0; tm < 4; tm++) {
        const int r = m0 + wm * 64 + tm * 16 + g;
        #pragma unroll
        for (int tn = 0; tn < 4; tn++) {
            const int col = n0 + wn * 32 + tn * 8 + 2 * c;
            const float b0 = __ldg(&bias[col]);
            const float b1 = __ldg(&bias[col + 1]);
            const float o00 = acc[tm][tn][0] + b0, o01 = acc[tm][tn][1] + b1;
            const float o10 = acc[tm][tn][2] + b0, o11 = acc[tm][tn][3] + b1;
            if (outHalf) {
                // head-blocked layout: [(col>>5)][row][col&31]
                const size_t hb = (size_t)(col >> 5) * ((size_t)TOKENS * 32)
                                + (size_t)(col & 31);
                uint32_t hi, lo;
                split2(o00, o01, hi, lo);
                *(uint32_t*)(CH + hb + (size_t)r * 32) = hi;
                *(uint32_t*)(CL + hb + (size_t)r * 32) = lo;
                split2(o10, o11, hi, lo);
                *(uint32_t*)(CH + hb + (size_t)(r + 8) * 32) = hi;
                *(uint32_t*)(CL + hb + (size_t)(r + 8) * 32) = lo;
            } else {
                *(float2*)(Cf + (size_t)r * N + col)       = make_float2(o00, o01);
                *(float2*)(Cf + (size_t)(r + 8) * N + col) = make_float2(o10, o11);
            }
        }
    }
}

// ---------------------------------------------------------------------------
// Tensor-core windowed attention, 6 heads per block, double-buffered cp.async.
// Block = (bn, head-group of 6); 128 threads / 4 warps.
// ---------------------------------------------------------------------------
#define HPB 6
#define VPITCH 40    // halves per row for Q/K/V planes (80B, LDSM conflict-free)
#define PPITCH 72    // halves per row for P planes (144B, conflict-free)
// per-buffer plane offsets (halves):
#define OFF_QH 0
#define OFF_QL 2560
#define OFF_KH 5120
#define OFF_KL 7680
#define OFF_VH 10240
#define OFF_VL 12800
#define BUF_HALVES 15360
// shared P planes + bias cache:
#define OFF_PH 30720
#define OFF_PL 35328
#define OFF_SBIAS 39936         // 169 floats = 338 halves
#define SMEM_HALVES 40288
#define SM_ATTN_TOTAL (SMEM_HALVES * 2)   // 80576 bytes

__global__ __launch_bounds__(128)
void attn_mma(const __half* __restrict__ qkvH, const __half* __restrict__ qkvL,
              const float* __restrict__ mask, const float* __restrict__ bias_table,
              __half* __restrict__ ctxH, __half* __restrict__ ctxL)
{
    extern __shared__ __half sh[];
    const uint32_t smb = smem_u32(sh);
    float* sbias = (float*)(sh + OFF_SBIAS);

    const int blk   = blockIdx.x;
    const int bn    = blk >> 1;
    const int hbase = (blk & 1) * HPB;
    const int tid = threadIdx.x;
    const int w    = tid >> 5;
    const int lane = tid & 31;
    const int g    = lane >> 2;
    const int cq   = lane & 3;
    const int m_idx = lane >> 3;
    const int rin   = lane & 7;

    // zero all smem once per block (pads must be 0; loads never touch pads)
    for (int i = tid; i < SMEM_HALVES / 8; i += 128)
        *(uint4*)(sh + (size_t)i * 8) = make_uint4(0u, 0u, 0u, 0u);
    __syncthreads();

    const size_t tokbase = (size_t)bn * NTOK;

    // coalesced head-slice gather: 6 planes x 49 rows x 4 chunks = 1176 x 16B
    auto issue_qkv = [&](int head, int buf) {
        #pragma unroll 1
        for (int e = tid; e < 1176; e += 128) {
            const int p   = e / 392;
            const int rem = e - p * 392;
            const int pl  = rem / 196;
            const int ch  = rem - pl * 196;
            const int r   = ch >> 2;
            const int c4  = ch & 3;
            const __half* src = (pl ? qkvL : qkvH)
                + (((size_t)(p * NHEADS + head) * TOKENS + tokbase + r) << 5) + c4 * 8;
            const uint32_t dst = smb + 2u * (uint32_t)(buf * BUF_HALVES + p * 5120
                               + pl * 2560 + r * VPITCH + c4 * 8);
            CP_ASYNC16(dst, src);
        }
        CP_COMMIT();
    };

    issue_qkv(hbase + 0, 0);
    issue_qkv(hbase + 1, 1);

    const float scale = 0.17677669529663687f;
    const float* mrow = mask + (size_t)(bn >> 6) * (NTOK * NTOK);

    for (int t = 0; t < HPB; t++) {
        const int h   = hbase + t;
        const uint32_t bofs = (uint32_t)((t & 1) * BUF_HALVES);

        if (t < HPB - 1) { CP_WAIT(1); } else { CP_WAIT(0); }
        // per-head bias cache
        for (int e = tid; e < 169; e += 128) sbias[e] = bias_table[e * NHEADS + h];
        __syncthreads();

        // ---- QK^T ----
        float acc[7][4];
        #pragma unroll
        for (int nt = 0; nt < 7; nt++)
            #pragma unroll
            for (int r = 0; r < 4; r++) acc[nt][r] = 0.f;

        uint32_t qh[2][4], ql[2][4];
        #pragma unroll
        for (int kt = 0; kt < 2; kt++) {
            const uint32_t a = smb + 2u * (uint32_t)(bofs
                             + (16 * w + (m_idx & 1) * 8 + rin) * VPITCH
                             + (m_idx >> 1) * 8 + kt * 16);
            ldmx4(qh[kt], a + 2u * OFF_QH);
            ldmx4(ql[kt], a + 2u * OFF_QL);
        }

        uint32_t kf[2][4][4];
        #pragma unroll
        for (int kt = 0; kt < 2; kt++)
            #pragma unroll
            for (int p = 0; p < 4; p++) {
                const uint32_t a = smb + 2u * (uint32_t)(bofs + OFF_KH
                                 + (16 * p + (m_idx >> 1) * 8 + rin) * VPITCH
                                 + (m_idx & 1) * 8 + kt * 16);
                ldmx4(kf[kt][p], a);
            }
        #pragma unroll
        for (int kt = 0; kt < 2; kt++)
            #pragma unroll
            for (int p = 0; p < 4; p++) {
                uint32_t b0[2] = { kf[kt][p][0], kf[kt][p][1] };
                uint32_t b1[2] = { kf[kt][p][2], kf[kt][p][3] };
                mma_f16(acc[2 * p], qh[kt], b0);
                mma_f16(acc[2 * p], ql[kt], b0);
                if (p < 3) {
                    mma_f16(acc[2 * p + 1], qh[kt], b1);
                    mma_f16(acc[2 * p + 1], ql[kt], b1);
                }
            }
        #pragma unroll
        for (int kt = 0; kt < 2; kt++)
            #pragma unroll
            for (int p = 0; p < 4; p++) {
                const uint32_t a = smb + 2u * (uint32_t)(bofs + OFF_KL
                                 + (16 * p + (m_idx >> 1) * 8 + rin) * VPITCH
                                 + (m_idx & 1) * 8 + kt * 16);
                ldmx4(kf[kt][p], a);
            }
        #pragma unroll
        for (int kt = 0; kt < 2; kt++)
            #pragma unroll
            for (int p = 0; p < 4; p++) {
                uint32_t b0[2] = { kf[kt][p][0], kf[kt][p][1] };
                uint32_t b1[2] = { kf[kt][p][2], kf[kt][p][3] };
                mma_f16(acc[2 * p], qh[kt], b0);
                if (p < 3) mma_f16(acc[2 * p + 1], qh[kt], b1);
            }

        // ---- softmax in fragments ----
        const int i0 = 16 * w + g, i1 = i0 + 8;

        float sv[7][4];
        float mm0 = -1e30f, mm1 = -1e30f;
        #pragma unroll
        for (int nt = 0; nt < 7; nt++) {
            #pragma unroll
            for (int r = 0; r < 4; r++) {
                const int i = (r < 2) ? i0 : i1;
                const int j = 8 * nt + 2 * cq + (r & 1);
                float s;
                if (i >= NTOK) s = 0.f;
                else if (j >= NTOK) s = -1e30f;
                else {
                    const int ih = i / 7, iw = i - ih * 7;
                    const int jh = j / 7, jw = j - jh * 7;
                    const int ridx = (ih - jh + 6) * 13 + (iw - jw + 6);
                    s = acc[nt][r] * scale + sbias[ridx] + __ldg(&mrow[i * NTOK + j]);
                }
                sv[nt][r] = s;
                if (r < 2) mm0 = fmaxf(mm0, s); else mm1 = fmaxf(mm1, s);
            }
        }
        mm0 = fmaxf(mm0, __shfl_xor_sync(0xffffffffu, mm0, 1));
        mm0 = fmaxf(mm0, __shfl_xor_sync(0xffffffffu, mm0, 2));
        mm1 = fmaxf(mm1, __shfl_xor_sync(0xffffffffu, mm1, 1));
        mm1 = fmaxf(mm1, __shfl_xor_sync(0xffffffffu, mm1, 2));

        float s0 = 0.f, s1 = 0.f;
        #pragma unroll
        for (int nt = 0; nt < 7; nt++) {
            #pragma unroll
            for (int r = 0; r < 4; r++) {
                const int i = (r < 2) ? i0 : i1;
                const int j = 8 * nt + 2 * cq + (r & 1);
                const float e = __expf(sv[nt][r] - ((r < 2) ? mm0 : mm1));
                if (r < 2) s0 += e; else s1 += e;
                const __half eh = __float2half_rn(e);
                const float  el = e - __half2float(eh);
                sh[OFF_PH + i * PPITCH + j] = eh;
                sh[OFF_PL + i * PPITCH + j] = __float2half_rn(el);
            }
        }
        s0 += __shfl_xor_sync(0xffffffffu, s0, 1);
        s0 += __shfl_xor_sync(0xffffffffu, s0, 2);
        s1 += __shfl_xor_sync(0xffffffffu, s1, 1);
        s1 += __shfl_xor_sync(0xffffffffu, s1, 2);
        const float inv0 = 1.f / s0;
        const float inv1 = 1.f / s1;

        __syncthreads();

        // ---- PV ----
        float pv[4][4];
        #pragma unroll
        for (int nt = 0; nt < 4; nt++)
            #pragma unroll
            for (int r = 0; r < 4; r++) pv[nt][r] = 0.f;

        uint32_t pf[4][4];
        uint32_t vf[4][2][4];

        const uint32_t pARow = (uint32_t)((16 * w + (m_idx & 1) * 8 + rin) * PPITCH
                             + (m_idx >> 1) * 8);
        // Ph x Vh
        #pragma unroll
        for (int kt = 0; kt < 4; kt++)
            ldmx4(pf[kt], smb + 2u * (uint32_t)(OFF_PH + pARow + kt * 16));
        #pragma unroll
        for (int kt = 0; kt < 4; kt++)
            #pragma unroll
            for (int dp = 0; dp < 2; dp++) {
                const uint32_t a = smb + 2u * (uint32_t)(bofs + OFF_VH
                                 + (16 * kt + (m_idx & 1) * 8 + rin) * VPITCH
                                 + (m_idx >> 1) * 8 + dp * 16);
                ldmx4t(vf[kt][dp], a);
            }
        #pragma unroll
        for (int kt = 0; kt < 4; kt++)
            #pragma unroll
            for (int dp = 0; dp < 2; dp++) {
                uint32_t b0[2] = { vf[kt][dp][0], vf[kt][dp][1] };
                uint32_t b1[2] = { vf[kt][dp][2], vf[kt][dp][3] };
                mma_f16(pv[2 * dp], pf[kt], b0);
                mma_f16(pv[2 * dp + 1], pf[kt], b1);
            }
        // Pl x Vh
        #pragma unroll
        for (int kt = 0; kt < 4; kt++)
            ldmx4(pf[kt], smb + 2u * (uint32_t)(OFF_PL + pARow + kt * 16));
        #pragma unroll
        for (int kt = 0; kt < 4; kt++)
            #pragma unroll
            for (int dp = 0; dp < 2; dp++) {
                uint32_t b0[2] = { vf[kt][dp][0], vf[kt][dp][1] };
                uint32_t b1[2] = { vf[kt][dp][2], vf[kt][dp][3] };
                mma_f16(pv[2 * dp], pf[kt], b0);
                mma_f16(pv[2 * dp + 1], pf[kt], b1);
            }
        // Ph x Vl
        #pragma unroll
        for (int kt = 0; kt < 4; kt++)
            ldmx4(pf[kt], smb + 2u * (uint32_t)(OFF_PH + pARow + kt * 16));
        #pragma unroll
        for (int kt = 0; kt < 4; kt++)
            #pragma unroll
            for (int dp = 0; dp < 2; dp++) {
                const uint32_t a = smb + 2u * (uint32_t)(bofs + OFF_VL
                                 + (16 * kt + (m_idx & 1) * 8 + rin) * VPITCH
                                 + (m_idx >> 1) * 8 + dp * 16);
                ldmx4t(vf[kt][dp], a);
            }
        #pragma unroll
        for (int kt = 0; kt < 4; kt++)
            #pragma unroll
            for (int dp = 0; dp < 2; dp++) {
                uint32_t b0[2] = { vf[kt][dp][0], vf[kt][dp][1] };
                uint32_t b1[2] = { vf[kt][dp][2], vf[kt][dp][3] };
                mma_f16(pv[2 * dp], pf[kt], b0);
                mma_f16(pv[2 * dp + 1], pf[kt], b1);
            }

        // ---- epilogue: normalize, split, store ctx hi/lo (row-major ctx) ----
        const size_t ob = (size_t)bn * NTOK * DIM + (size_t)h * DHEAD;
        if (i0 < NTOK) {
            #pragma unroll
            for (int nt = 0; nt < 4; nt++) {
                const int d = 8 * nt + 2 * cq;
                uint32_t hi, lo;
                split2(pv[nt][0] * inv0, pv[nt][1] * inv0, hi, lo);
                *(uint32_t*)(ctxH + ob + (size_t)i0 * DIM + d) = hi;
                *(uint32_t*)(ctxL + ob + (size_t)i0 * DIM + d) = lo;
            }
        }
        if (i1 < NTOK) {
            #pragma unroll
            for (int nt = 0; nt < 4; nt++) {
                const int d = 8 * nt + 2 * cq;
                uint32_t hi, lo;
                split2(pv[nt][2] * inv1, pv[nt][3] * inv1, hi, lo);
                *(uint32_t*)(ctxH + ob + (size_t)i1 * DIM + d) = hi;
                *(uint32_t*)(ctxL + ob + (size_t)i1 * DIM + d) = lo;
            }
        }

        __syncthreads();   // all reads of this buffer + P done

        if (t + 2 < HPB) issue_qkv(hbase + t + 2, t & 1);
    }
}

// ---------------------------------------------------------------------------
extern "C" void kernel_launch(void* const* d_in, const int* in_sizes, int n_in,
                              void* d_out, int out_size)
{
    const float* x          = (const float*)d_in[0];
    const float* mask       = (const float*)d_in[1];
    const float* w_qkv      = (const float*)d_in[2];
    const float* b_qkv      = (const float*)d_in[3];
    const float* w_proj     = (const float*)d_in[4];
    const float* b_proj     = (const float*)d_in[5];
    const float* bias_table = (const float*)d_in[6];
    float* out = (float*)d_out;

    __half *qkvH, *qkvL, *xH, *xL, *ctxH, *ctxL, *wqH, *wqL, *wpH, *wpL;
    cudaGetSymbolAddress((void**)&qkvH, g_qkvH);
    cudaGetSymbolAddress((void**)&qkvL, g_qkvL);
    cudaGetSymbolAddress((void**)&xH,   g_xH);
    cudaGetSymbolAddress((void**)&xL,   g_xL);
    cudaGetSymbolAddress((void**)&ctxH, g_ctxH);
    cudaGetSymbolAddress((void**)&ctxL, g_ctxL);
    cudaGetSymbolAddress((void**)&wqH,  g_wqkvH);
    cudaGetSymbolAddress((void**)&wqL,  g_wqkvL);
    cudaGetSymbolAddress((void**)&wpH,  g_wprojH);
    cudaGetSymbolAddress((void**)&wpL,  g_wprojL);

    cudaFuncSetAttribute(gemm_hilo_nt, cudaFuncAttributeMaxDynamicSharedMemorySize, SM_GEMM_TOTAL);
    cudaFuncSetAttribute(attn_mma, cudaFuncAttributeMaxDynamicSharedMemorySize, SM_ATTN_TOTAL);

    // 0) split inputs/weights into fp16 hi/lo planes
    split_kernel<<<1184, 256>>>(x, xH, xL, (size_t)TOKENS * DIM / 4);
    split_kernel<<<432, 256>>>(w_qkv, wqH, wqL, (size_t)QKV_COLS * DIM / 4);
    split_kernel<<<144, 256>>>(w_proj, wpH, wpL, (size_t)DIM * DIM / 4);

    // 1) QKV projection -> head-blocked fp16 hi/lo planes
    {
        dim3 grid(QKV_COLS / 128, TOKENS / 128);
        gemm_hilo_nt<<<grid, 256, SM_GEMM_TOTAL>>>(xH, xL, wqH, wqL, b_qkv,
                                                   nullptr, qkvH, qkvL,
                                                   TOKENS, QKV_COLS, DIM, 1);
    }
    // 2) tensor-core windowed attention (6 heads/block, double-buffered)
    attn_mma<<<BN_TOTAL * 2, 128, SM_ATTN_TOTAL>>>(qkvH, qkvL, mask, bias_table,
                                                   ctxH, ctxL);
    // 3) output projection -> fp32 out
    {
        dim3 grid(DIM / 128, TOKENS / 128);
        gemm_hilo_nt<<<grid, 256, SM_GEMM_TOTAL>>>(ctxH, ctxL, wpH, wpL, b_proj,
                                                   out, nullptr, nullptr,
                                                   TOKENS, DIM, DIM, 0);
    }
}

// round 9
// speedup vs baseline: 2.2375x; 1.2875x over previous
#include <cuda_runtime.h>
#include <cuda_fp16.h>
#include <cstdint>
#include <cstddef>

// ---------------------------------------------------------------------------
// Problem constants
// ---------------------------------------------------------------------------
#define NHEADS   12
#define DHEAD    32
#define NTOK     49
#define DIM      384
#define BN_TOTAL 4096
#define TOKENS   (BN_TOTAL * NTOK)   // 200704
#define QKV_COLS 1152

// Scratch (allocation-free rule: device globals)
// qkv planes stored head-blocked: [(comp*12+head)][token][32]
__device__ __half g_qkvH[(size_t)TOKENS * QKV_COLS];
__device__ __half g_qkvL[(size_t)TOKENS * QKV_COLS];
__device__ __half g_xH[(size_t)TOKENS * DIM];
__device__ __half g_xL[(size_t)TOKENS * DIM];
__device__ __half g_ctxH[(size_t)TOKENS * DIM];
__device__ __half g_ctxL[(size_t)TOKENS * DIM];
__device__ __half g_wqkvH[(size_t)QKV_COLS * DIM];
__device__ __half g_wprojH[(size_t)DIM * DIM];

// ---------------------------------------------------------------------------
// Common device helpers
// ---------------------------------------------------------------------------
__device__ __forceinline__ void split2(float x, float y, uint32_t& hi, uint32_t& lo) {
    half2 h = __floats2half2_rn(x, y);
    float rx = x - __low2float(h);
    float ry = y - __high2float(h);
    half2 l = __floats2half2_rn(rx, ry);
    hi = *(uint32_t*)&h;
    lo = *(uint32_t*)&l;
}

__device__ __forceinline__ void mma_f16(float* d, const uint32_t* a, const uint32_t* b) {
    asm volatile(
        "mma.sync.aligned.m16n8k16.row.col.f32.f16.f16.f32 "
        "{%0,%1,%2,%3}, {%4,%5,%6,%7}, {%8,%9}, {%0,%1,%2,%3};"
        : "+f"(d[0]), "+f"(d[1]), "+f"(d[2]), "+f"(d[3])
        : "r"(a[0]), "r"(a[1]), "r"(a[2]), "r"(a[3]), "r"(b[0]), "r"(b[1]));
}

__device__ __forceinline__ void ldmx4(uint32_t* r, uint32_t addr) {
    asm volatile("ldmatrix.sync.aligned.m8n8.x4.shared.b16 {%0,%1,%2,%3}, [%4];"
        : "=r"(r[0]), "=r"(r[1]), "=r"(r[2]), "=r"(r[3]) : "r"(addr));
}
__device__ __forceinline__ void ldmx4t(uint32_t* r, uint32_t addr) {
    asm volatile("ldmatrix.sync.aligned.m8n8.x4.trans.shared.b16 {%0,%1,%2,%3}, [%4];"
        : "=r"(r[0]), "=r"(r[1]), "=r"(r[2]), "=r"(r[3]) : "r"(addr));
}

__device__ __forceinline__ uint32_t smem_u32(const void* p) {
    uint32_t a;
    asm("{ .reg .u64 t; cvta.to.shared.u64 t, %1; cvt.u32.u64 %0, t; }"
        : "=r"(a) : "l"(p));
    return a;
}

#define CP_ASYNC16(dst, src) \
    asm volatile("cp.async.cg.shared.global [%0], [%1], 16;" :: "r"(dst), "l"(src))
#define CP_COMMIT() asm volatile("cp.async.commit_group;" ::: "memory")
#define CP_WAIT(n)  asm volatile("cp.async.wait_group %0;" :: "n"(n) : "memory")

// ---------------------------------------------------------------------------
// Prep kernels
// ---------------------------------------------------------------------------
__global__ void split_kernel(const float* __restrict__ src,
                             __half* __restrict__ hi, __half* __restrict__ lo,
                             size_t n4)
{
    const size_t stride = (size_t)gridDim.x * blockDim.x;
    for (size_t i = (size_t)blockIdx.x * blockDim.x + threadIdx.x; i < n4; i += stride) {
        float4 v = *((const float4*)src + i);
        uint32_t h01, l01, h23, l23;
        split2(v.x, v.y, h01, l01);
        split2(v.z, v.w, h23, l23);
        *(uint2*)(hi + i * 4) = make_uint2(h01, h23);
        *(uint2*)(lo + i * 4) = make_uint2(l01, l23);
    }
}

__global__ void cvt_kernel(const float* __restrict__ src,
                           __half* __restrict__ hi, size_t n4)
{
    const size_t stride = (size_t)gridDim.x * blockDim.x;
    for (size_t i = (size_t)blockIdx.x * blockDim.x + threadIdx.x; i < n4; i += stride) {
        float4 v = *((const float4*)src + i);
        half2 h01 = __floats2half2_rn(v.x, v.y);
        half2 h23 = __floats2half2_rn(v.z, v.w);
        *(uint2*)(hi + i * 4) = make_uint2(*(uint32_t*)&h01, *(uint32_t*)&h23);
    }
}

// ---------------------------------------------------------------------------
// 2-term fp16 GEMM (NT): C = (AH+AL) * BH^T + bias  (B rounded to fp16 RN).
// BM=BN=128, BK=32, 3-stage cp.async pipeline, 3 smem planes (AH, AL, BH),
// row pitch 80B (conflict-free LDSM), 256 threads, 2 CTAs/SM.
// ---------------------------------------------------------------------------
#define GBM 128
#define GBK 32
#define GPITCH 80                         // bytes per 32-half row (64B data + 16 pad)
#define PL_BYTES (128 * GPITCH)           // 10240
#define BUF_BYTES (3 * PL_BYTES)          // 30720
#define NSTAGE 3
#define SM_GEMM_TOTAL (NSTAGE * BUF_BYTES)   // 92160

__global__ __launch_bounds__(256, 2)
void gemm_2t(const __half* __restrict__ AH, const __half* __restrict__ AL,
             const __half* __restrict__ BH,
             const float* __restrict__ bias,
             float* __restrict__ Cf,
             __half* __restrict__ CH, __half* __restrict__ CL,
             int M, int N, int K, int outHalf)
{
    extern __shared__ char sm[];
    const uint32_t smb = smem_u32(sm);

    const int tid  = threadIdx.x;
    const int wid  = tid >> 5;
    const int lane = tid & 31;
    const int g = lane >> 2;
    const int c = lane & 3;
    const int wm = wid & 1;
    const int wn = wid >> 1;

    const int m0 = blockIdx.y * GBM;
    const int n0 = blockIdx.x * GBM;

    // staging: thread t: row sr = t>>1, 32B half-row sc = t&1 (two 16B chunks)
    const int sr = tid >> 1;
    const int sc = tid & 1;
    const __half* gA_H = AH + (size_t)(m0 + sr) * K + sc * 16;
    const __half* gA_L = AL + (size_t)(m0 + sr) * K + sc * 16;
    const __half* gB_H = BH + (size_t)(n0 + sr) * K + sc * 16;
    const uint32_t dstOff = (uint32_t)sr * GPITCH + (uint32_t)sc * 32;

    const int m_idx = lane >> 3;
    const int rin   = lane & 7;
    const uint32_t aRowOff = (uint32_t)(wm * 64 + (m_idx & 1) * 8 + rin) * GPITCH
                           + (uint32_t)(m_idx >> 1) * 16;
    const uint32_t bRowOff = (uint32_t)(wn * 32 + (m_idx >> 1) * 8 + rin) * GPITCH
                           + (uint32_t)(m_idx & 1) * 16;

    float acc[4][4][4];
    #pragma unroll
    for (int i = 0; i < 4; i++)
        #pragma unroll
        for (int j = 0; j < 4; j++)
            #pragma unroll
            for (int r = 0; r < 4; r++) acc[i][j][r] = 0.f;

    const int NK = K / GBK;   // 12

    // prologue: stage chunks 0 and 1
    #pragma unroll
    for (int s = 0; s < 2; s++) {
        const uint32_t dst = smb + (uint32_t)s * BUF_BYTES + dstOff;
        const size_t go = (size_t)s * GBK;
        CP_ASYNC16(dst + 0 * PL_BYTES,      gA_H + go);
        CP_ASYNC16(dst + 0 * PL_BYTES + 16, gA_H + go + 8);
        CP_ASYNC16(dst + 1 * PL_BYTES,      gA_L + go);
        CP_ASYNC16(dst + 1 * PL_BYTES + 16, gA_L + go + 8);
        CP_ASYNC16(dst + 2 * PL_BYTES,      gB_H + go);
        CP_ASYNC16(dst + 2 * PL_BYTES + 16, gB_H + go + 8);
        CP_COMMIT();
    }

    int cur = 0, nx2 = 2;
    for (int kt = 0; kt < NK; kt++) {
        if (kt + 1 < NK) { CP_WAIT(1); } else { CP_WAIT(0); }
        __syncthreads();

        if (kt + 2 < NK) {
            const uint32_t dst = smb + (uint32_t)nx2 * BUF_BYTES + dstOff;
            const size_t go = (size_t)(kt + 2) * GBK;
            CP_ASYNC16(dst + 0 * PL_BYTES,      gA_H + go);
            CP_ASYNC16(dst + 0 * PL_BYTES + 16, gA_H + go + 8);
            CP_ASYNC16(dst + 1 * PL_BYTES,      gA_L + go);
            CP_ASYNC16(dst + 1 * PL_BYTES + 16, gA_L + go + 8);
            CP_ASYNC16(dst + 2 * PL_BYTES,      gB_H + go);
            CP_ASYNC16(dst + 2 * PL_BYTES + 16, gB_H + go + 8);
            CP_COMMIT();
        }

        const uint32_t bufB = smb + (uint32_t)cur * BUF_BYTES;

        #pragma unroll
        for (int ks = 0; ks < 2; ks++) {
            const uint32_t ko = (uint32_t)ks * 32;

            // B fragments (H plane only)
            uint32_t bfr[4][2];
            #pragma unroll
            for (int nn = 0; nn < 2; nn++) {
                uint32_t r4[4];
                ldmx4(r4, bufB + 2 * PL_BYTES + bRowOff + (uint32_t)nn * 16 * GPITCH + ko);
                bfr[2 * nn][0] = r4[0]; bfr[2 * nn][1] = r4[1];
                bfr[2 * nn + 1][0] = r4[2]; bfr[2 * nn + 1][1] = r4[3];
            }

            uint32_t af[4][4];
            // A hi
            #pragma unroll
            for (int tm = 0; tm < 4; tm++)
                ldmx4(af[tm], bufB + 0 * PL_BYTES + aRowOff + (uint32_t)tm * 16 * GPITCH + ko);
            #pragma unroll
            for (int tm = 0; tm < 4; tm++)
                #pragma unroll
                for (int tn = 0; tn < 4; tn++)
                    mma_f16(acc[tm][tn], af[tm], bfr[tn]);
            // A lo
            #pragma unroll
            for (int tm = 0; tm < 4; tm++)
                ldmx4(af[tm], bufB + 1 * PL_BYTES + aRowOff + (uint32_t)tm * 16 * GPITCH + ko);
            #pragma unroll
            for (int tm = 0; tm < 4; tm++)
                #pragma unroll
                for (int tn = 0; tn < 4; tn++)
                    mma_f16(acc[tm][tn], af[tm], bfr[tn]);
        }

        cur = (cur == 2) ? 0 : cur + 1;
        nx2 = (nx2 == 2) ? 0 : nx2 + 1;
    }

    // ---- epilogue ----
    #pragma unroll
    for (int tm = 0; tm < 4; tm++) {
        const int r = m0 + wm * 64 + tm * 16 + g;
        #pragma unroll
        for (int tn = 0; tn < 4; tn++) {
            const int col = n0 + wn * 32 + tn * 8 + 2 * c;
            const float b0 = __ldg(&bias[col]);
            const float b1 = __ldg(&bias[col + 1]);
            const float o00 = acc[tm][tn][0] + b0, o01 = acc[tm][tn][1] + b1;
            const float o10 = acc[tm][tn][2] + b0, o11 = acc[tm][tn][3] + b1;
            if (outHalf) {
                // head-blocked layout: [(col>>5)][row][col&31]
                const size_t hb = (size_t)(col >> 5) * ((size_t)TOKENS * 32)
                                + (size_t)(col & 31);
                uint32_t hi, lo;
                split2(o00, o01, hi, lo);
                *(uint32_t*)(CH + hb + (size_t)r * 32) = hi;
                *(uint32_t*)(CL + hb + (size_t)r * 32) = lo;
                split2(o10, o11, hi, lo);
                *(uint32_t*)(CH + hb + (size_t)(r + 8) * 32) = hi;
                *(uint32_t*)(CL + hb + (size_t)(r + 8) * 32) = lo;
            } else {
                *(float2*)(Cf + (size_t)r * N + col)       = make_float2(o00, o01);
                *(float2*)(Cf + (size_t)(r + 8) * N + col) = make_float2(o10, o11);
            }
        }
    }
}

// ---------------------------------------------------------------------------
// Tensor-core windowed attention, 6 heads per block, double-buffered cp.async.
// Block = (bn, head-group of 6); 128 threads / 4 warps. (3-term, unchanged.)
// ---------------------------------------------------------------------------
#define HPB 6
#define VPITCH 40
#define PPITCH 72
#define OFF_QH 0
#define OFF_QL 2560
#define OFF_KH 5120
#define OFF_KL 7680
#define OFF_VH 10240
#define OFF_VL 12800
#define BUF_HALVES 15360
#define OFF_PH 30720
#define OFF_PL 35328
#define OFF_SBIAS 39936
#define SMEM_HALVES 40288
#define SM_ATTN_TOTAL (SMEM_HALVES * 2)   // 80576 bytes

__global__ __launch_bounds__(128)
void attn_mma(const __half* __restrict__ qkvH, const __half* __restrict__ qkvL,
              const float* __restrict__ mask, const float* __restrict__ bias_table,
              __half* __restrict__ ctxH, __half* __restrict__ ctxL)
{
    extern __shared__ __half sh[];
    const uint32_t smb = smem_u32(sh);
    float* sbias = (float*)(sh + OFF_SBIAS);

    const int blk   = blockIdx.x;
    const int bn    = blk >> 1;
    const int hbase = (blk & 1) * HPB;
    const int tid = threadIdx.x;
    const int w    = tid >> 5;
    const int lane = tid & 31;
    const int g    = lane >> 2;
    const int cq   = lane & 3;
    const int m_idx = lane >> 3;
    const int rin   = lane & 7;

    for (int i = tid; i < SMEM_HALVES / 8; i += 128)
        *(uint4*)(sh + (size_t)i * 8) = make_uint4(0u, 0u, 0u, 0u);
    __syncthreads();

    const size_t tokbase = (size_t)bn * NTOK;

    auto issue_qkv = [&](int head, int buf) {
        #pragma unroll 1
        for (int e = tid; e < 1176; e += 128) {
            const int p   = e / 392;
            const int rem = e - p * 392;
            const int pl  = rem / 196;
            const int ch  = rem - pl * 196;
            const int r   = ch >> 2;
            const int c4  = ch & 3;
            const __half* src = (pl ? qkvL : qkvH)
                + (((size_t)(p * NHEADS + head) * TOKENS + tokbase + r) << 5) + c4 * 8;
            const uint32_t dst = smb + 2u * (uint32_t)(buf * BUF_HALVES + p * 5120
                               + pl * 2560 + r * VPITCH + c4 * 8);
            CP_ASYNC16(dst, src);
        }
        CP_COMMIT();
    };

    issue_qkv(hbase + 0, 0);
    issue_qkv(hbase + 1, 1);

    const float scale = 0.17677669529663687f;
    const float* mrow = mask + (size_t)(bn >> 6) * (NTOK * NTOK);

    for (int t = 0; t < HPB; t++) {
        const int h   = hbase + t;
        const uint32_t bofs = (uint32_t)((t & 1) * BUF_HALVES);

        if (t < HPB - 1) { CP_WAIT(1); } else { CP_WAIT(0); }
        for (int e = tid; e < 169; e += 128) sbias[e] = bias_table[e * NHEADS + h];
        __syncthreads();

        // ---- QK^T ----
        float acc[7][4];
        #pragma unroll
        for (int nt = 0; nt < 7; nt++)
            #pragma unroll
            for (int r = 0; r < 4; r++) acc[nt][r] = 0.f;

        uint32_t qh[2][4], ql[2][4];
        #pragma unroll
        for (int kt = 0; kt < 2; kt++) {
            const uint32_t a = smb + 2u * (uint32_t)(bofs
                             + (16 * w + (m_idx & 1) * 8 + rin) * VPITCH
                             + (m_idx >> 1) * 8 + kt * 16);
            ldmx4(qh[kt], a + 2u * OFF_QH);
            ldmx4(ql[kt], a + 2u * OFF_QL);
        }

        uint32_t kf[2][4][4];
        #pragma unroll
        for (int kt = 0; kt < 2; kt++)
            #pragma unroll
            for (int p = 0; p < 4; p++) {
                const uint32_t a = smb + 2u * (uint32_t)(bofs + OFF_KH
                                 + (16 * p + (m_idx >> 1) * 8 + rin) * VPITCH
                                 + (m_idx & 1) * 8 + kt * 16);
                ldmx4(kf[kt][p], a);
            }
        #pragma unroll
        for (int kt = 0; kt < 2; kt++)
            #pragma unroll
            for (int p = 0; p < 4; p++) {
                uint32_t b0[2] = { kf[kt][p][0], kf[kt][p][1] };
                uint32_t b1[2] = { kf[kt][p][2], kf[kt][p][3] };
                mma_f16(acc[2 * p], qh[kt], b0);
                mma_f16(acc[2 * p], ql[kt], b0);
                if (p < 3) {
                    mma_f16(acc[2 * p + 1], qh[kt], b1);
                    mma_f16(acc[2 * p + 1], ql[kt], b1);
                }
            }
        #pragma unroll
        for (int kt = 0; kt < 2; kt++)
            #pragma unroll
            for (int p = 0; p < 4; p++) {
                const uint32_t a = smb + 2u * (uint32_t)(bofs + OFF_KL
                                 + (16 * p + (m_idx >> 1) * 8 + rin) * VPITCH
                                 + (m_idx & 1) * 8 + kt * 16);
                ldmx4(kf[kt][p], a);
            }
        #pragma unroll
        for (int kt = 0; kt < 2; kt++)
            #pragma unroll
            for (int p = 0; p < 4; p++) {
                uint32_t b0[2] = { kf[kt][p][0], kf[kt][p][1] };
                uint32_t b1[2] = { kf[kt][p][2], kf[kt][p][3] };
                mma_f16(acc[2 * p], qh[kt], b0);
                if (p < 3) mma_f16(acc[2 * p + 1], qh[kt], b1);
            }

        // ---- softmax in fragments ----
        const int i0 = 16 * w + g, i1 = i0 + 8;

        float sv[7][4];
        float mm0 = -1e30f, mm1 = -1e30f;
        #pragma unroll
        for (int nt = 0; nt < 7; nt++) {
            #pragma unroll
            for (int r = 0; r < 4; r++) {
                const int i = (r < 2) ? i0 : i1;
                const int j = 8 * nt + 2 * cq + (r & 1);
                float s;
                if (i >= NTOK) s = 0.f;
                else if (j >= NTOK) s = -1e30f;
                else {
                    const int ih = i / 7, iw = i - ih * 7;
                    const int jh = j / 7, jw = j - jh * 7;
                    const int ridx = (ih - jh + 6) * 13 + (iw - jw + 6);
                    s = acc[nt][r] * scale + sbias[ridx] + __ldg(&mrow[i * NTOK + j]);
                }
                sv[nt][r] = s;
                if (r < 2) mm0 = fmaxf(mm0, s); else mm1 = fmaxf(mm1, s);
            }
        }
        mm0 = fmaxf(mm0, __shfl_xor_sync(0xffffffffu, mm0, 1));
        mm0 = fmaxf(mm0, __shfl_xor_sync(0xffffffffu, mm0, 2));
        mm1 = fmaxf(mm1, __shfl_xor_sync(0xffffffffu, mm1, 1));
        mm1 = fmaxf(mm1, __shfl_xor_sync(0xffffffffu, mm1, 2));

        float s0 = 0.f, s1 = 0.f;
        #pragma unroll
        for (int nt = 0; nt < 7; nt++) {
            #pragma unroll
            for (int r = 0; r < 4; r++) {
                const int i = (r < 2) ? i0 : i1;
                const int j = 8 * nt + 2 * cq + (r & 1);
                const float e = __expf(sv[nt][r] - ((r < 2) ? mm0 : mm1));
                if (r < 2) s0 += e; else s1 += e;
                const __half eh = __float2half_rn(e);
                const float  el = e - __half2float(eh);
                sh[OFF_PH + i * PPITCH + j] = eh;
                sh[OFF_PL + i * PPITCH + j] = __float2half_rn(el);
            }
        }
        s0 += __shfl_xor_sync(0xffffffffu, s0, 1);
        s0 += __shfl_xor_sync(0xffffffffu, s0, 2);
        s1 += __shfl_xor_sync(0xffffffffu, s1, 1);
        s1 += __shfl_xor_sync(0xffffffffu, s1, 2);
        const float inv0 = 1.f / s0;
        const float inv1 = 1.f / s1;

        __syncthreads();

        // ---- PV ----
        float pv[4][4];
        #pragma unroll
        for (int nt = 0; nt < 4; nt++)
            #pragma unroll
            for (int r = 0; r < 4; r++) pv[nt][r] = 0.f;

        uint32_t pf[4][4];
        uint32_t vf[4][2][4];

        const uint32_t pARow = (uint32_t)((16 * w + (m_idx & 1) * 8 + rin) * PPITCH
                             + (m_idx >> 1) * 8);
        #pragma unroll
        for (int kt = 0; kt < 4; kt++)
            ldmx4(pf[kt], smb + 2u * (uint32_t)(OFF_PH + pARow + kt * 16));
        #pragma unroll
        for (int kt = 0; kt < 4; kt++)
            #pragma unroll
            for (int dp = 0; dp < 2; dp++) {
                const uint32_t a = smb + 2u * (uint32_t)(bofs + OFF_VH
                                 + (16 * kt + (m_idx & 1) * 8 + rin) * VPITCH
                                 + (m_idx >> 1) * 8 + dp * 16);
                ldmx4t(vf[kt][dp], a);
            }
        #pragma unroll
        for (int kt = 0; kt < 4; kt++)
            #pragma unroll
            for (int dp = 0; dp < 2; dp++) {
                uint32_t b0[2] = { vf[kt][dp][0], vf[kt][dp][1] };
                uint32_t b1[2] = { vf[kt][dp][2], vf[kt][dp][3] };
                mma_f16(pv[2 * dp], pf[kt], b0);
                mma_f16(pv[2 * dp + 1], pf[kt], b1);
            }
        #pragma unroll
        for (int kt = 0; kt < 4; kt++)
            ldmx4(pf[kt], smb + 2u * (uint32_t)(OFF_PL + pARow + kt * 16));
        #pragma unroll
        for (int kt = 0; kt < 4; kt++)
            #pragma unroll
            for (int dp = 0; dp < 2; dp++) {
                uint32_t b0[2] = { vf[kt][dp][0], vf[kt][dp][1] };
                uint32_t b1[2] = { vf[kt][dp][2], vf[kt][dp][3] };
                mma_f16(pv[2 * dp], pf[kt], b0);
                mma_f16(pv[2 * dp + 1], pf[kt], b1);
            }
        #pragma unroll
        for (int kt = 0; kt < 4; kt++)
            ldmx4(pf[kt], smb + 2u * (uint32_t)(OFF_PH + pARow + kt * 16));
        #pragma unroll
        for (int kt = 0; kt < 4; kt++)
            #pragma unroll
            for (int dp = 0; dp < 2; dp++) {
                const uint32_t a = smb + 2u * (uint32_t)(bofs + OFF_VL
                                 + (16 * kt + (m_idx & 1) * 8 + rin) * VPITCH
                                 + (m_idx >> 1) * 8 + dp * 16);
                ldmx4t(vf[kt][dp], a);
            }
        #pragma unroll
        for (int kt = 0; kt < 4; kt++)
            #pragma unroll
            for (int dp = 0; dp < 2; dp++) {
                uint32_t b0[2] = { vf[kt][dp][0], vf[kt][dp][1] };
                uint32_t b1[2] = { vf[kt][dp][2], vf[kt][dp][3] };
                mma_f16(pv[2 * dp], pf[kt], b0);
                mma_f16(pv[2 * dp + 1], pf[kt], b1);
            }

        // ---- epilogue ----
        const size_t ob = (size_t)bn * NTOK * DIM + (size_t)h * DHEAD;
        if (i0 < NTOK) {
            #pragma unroll
            for (int nt = 0; nt < 4; nt++) {
                const int d = 8 * nt + 2 * cq;
                uint32_t hi, lo;
                split2(pv[nt][0] * inv0, pv[nt][1] * inv0, hi, lo);
                *(uint32_t*)(ctxH + ob + (size_t)i0 * DIM + d) = hi;
                *(uint32_t*)(ctxL + ob + (size_t)i0 * DIM + d) = lo;
            }
        }
        if (i1 < NTOK) {
            #pragma unroll
            for (int nt = 0; nt < 4; nt++) {
                const int d = 8 * nt + 2 * cq;
                uint32_t hi, lo;
                split2(pv[nt][2] * inv1, pv[nt][3] * inv1, hi, lo);
                *(uint32_t*)(ctxH + ob + (size_t)i1 * DIM + d) = hi;
                *(uint32_t*)(ctxL + ob + (size_t)i1 * DIM + d) = lo;
            }
        }

        __syncthreads();

        if (t + 2 < HPB) issue_qkv(hbase + t + 2, t & 1);
    }
}

// ---------------------------------------------------------------------------
extern "C" void kernel_launch(void* const* d_in, const int* in_sizes, int n_in,
                              void* d_out, int out_size)
{
    const float* x          = (const float*)d_in[0];
    const float* mask       = (const float*)d_in[1];
    const float* w_qkv      = (const float*)d_in[2];
    const float* b_qkv      = (const float*)d_in[3];
    const float* w_proj     = (const float*)d_in[4];
    const float* b_proj     = (const float*)d_in[5];
    const float* bias_table = (const float*)d_in[6];
    float* out = (float*)d_out;

    __half *qkvH, *qkvL, *xH, *xL, *ctxH, *ctxL, *wqH, *wpH;
    cudaGetSymbolAddress((void**)&qkvH, g_qkvH);
    cudaGetSymbolAddress((void**)&qkvL, g_qkvL);
    cudaGetSymbolAddress((void**)&xH,   g_xH);
    cudaGetSymbolAddress((void**)&xL,   g_xL);
    cudaGetSymbolAddress((void**)&ctxH, g_ctxH);
    cudaGetSymbolAddress((void**)&ctxL, g_ctxL);
    cudaGetSymbolAddress((void**)&wqH,  g_wqkvH);
    cudaGetSymbolAddress((void**)&wpH,  g_wprojH);

    cudaFuncSetAttribute(gemm_2t, cudaFuncAttributeMaxDynamicSharedMemorySize, SM_GEMM_TOTAL);
    cudaFuncSetAttribute(attn_mma, cudaFuncAttributeMaxDynamicSharedMemorySize, SM_ATTN_TOTAL);

    // 0) prep: split activations (hi+lo), convert weights (hi only, RN)
    split_kernel<<<1184, 256>>>(x, xH, xL, (size_t)TOKENS * DIM / 4);
    cvt_kernel<<<432, 256>>>(w_qkv, wqH, (size_t)QKV_COLS * DIM / 4);
    cvt_kernel<<<144, 256>>>(w_proj, wpH, (size_t)DIM * DIM / 4);

    // 1) QKV projection (2-term) -> head-blocked fp16 hi/lo planes
    {
        dim3 grid(QKV_COLS / 128, TOKENS / 128);
        gemm_2t<<<grid, 256, SM_GEMM_TOTAL>>>(xH, xL, wqH, b_qkv,
                                              nullptr, qkvH, qkvL,
                                              TOKENS, QKV_COLS, DIM, 1);
    }
    // 2) tensor-core windowed attention (3-term, unchanged)
    attn_mma<<<BN_TOTAL * 2, 128, SM_ATTN_TOTAL>>>(qkvH, qkvL, mask, bias_table,
                                                   ctxH, ctxL);
    // 3) output projection (2-term) -> fp32 out
    {
        dim3 grid(DIM / 128, TOKENS / 128);
        gemm_2t<<<grid, 256, SM_GEMM_TOTAL>>>(ctxH, ctxL, wpH, b_proj,
                                              out, nullptr, nullptr,
                                              TOKENS, DIM, DIM, 0);
    }
}

// round 10
// speedup vs baseline: 4.5466x; 2.0320x over previous
#include <cuda_runtime.h>
#include <cuda_fp16.h>
#include <cstdint>
#include <cstddef>

// ---------------------------------------------------------------------------
// Problem constants
// ---------------------------------------------------------------------------
#define NHEADS   12
#define DHEAD    32
#define NTOK     49
#define DIM      384
#define BN_TOTAL 4096
#define TOKENS   (BN_TOTAL * NTOK)   // 200704
#define QKV_COLS 1152

// Scratch (allocation-free rule: device globals)
// qkv stored head-blocked: [(comp*12+head)][token][32]
__device__ __half g_qkvH[(size_t)TOKENS * QKV_COLS];
__device__ __half g_xH[(size_t)TOKENS * DIM];
__device__ __half g_ctxH[(size_t)TOKENS * DIM];
__device__ __half g_wqkvH[(size_t)QKV_COLS * DIM];
__device__ __half g_wprojH[(size_t)DIM * DIM];

// ---------------------------------------------------------------------------
// Common device helpers
// ---------------------------------------------------------------------------
__device__ __forceinline__ void mma_f16(float* d, const uint32_t* a, const uint32_t* b) {
    asm volatile(
        "mma.sync.aligned.m16n8k16.row.col.f32.f16.f16.f32 "
        "{%0,%1,%2,%3}, {%4,%5,%6,%7}, {%8,%9}, {%0,%1,%2,%3};"
        : "+f"(d[0]), "+f"(d[1]), "+f"(d[2]), "+f"(d[3])
        : "r"(a[0]), "r"(a[1]), "r"(a[2]), "r"(a[3]), "r"(b[0]), "r"(b[1]));
}

__device__ __forceinline__ void ldmx4(uint32_t* r, uint32_t addr) {
    asm volatile("ldmatrix.sync.aligned.m8n8.x4.shared.b16 {%0,%1,%2,%3}, [%4];"
        : "=r"(r[0]), "=r"(r[1]), "=r"(r[2]), "=r"(r[3]) : "r"(addr));
}
__device__ __forceinline__ void ldmx4t(uint32_t* r, uint32_t addr) {
    asm volatile("ldmatrix.sync.aligned.m8n8.x4.trans.shared.b16 {%0,%1,%2,%3}, [%4];"
        : "=r"(r[0]), "=r"(r[1]), "=r"(r[2]), "=r"(r[3]) : "r"(addr));
}

__device__ __forceinline__ uint32_t smem_u32(const void* p) {
    uint32_t a;
    asm("{ .reg .u64 t; cvta.to.shared.u64 t, %1; cvt.u32.u64 %0, t; }"
        : "=r"(a) : "l"(p));
    return a;
}

#define CP_ASYNC16(dst, src) \
    asm volatile("cp.async.cg.shared.global [%0], [%1], 16;" :: "r"(dst), "l"(src))
#define CP_COMMIT() asm volatile("cp.async.commit_group;" ::: "memory")
#define CP_WAIT(n)  asm volatile("cp.async.wait_group %0;" :: "n"(n) : "memory")

// ---------------------------------------------------------------------------
// Prep: fp32 -> fp16 RN convert
// ---------------------------------------------------------------------------
__global__ void cvt_kernel(const float* __restrict__ src,
                           __half* __restrict__ hi, size_t n4)
{
    const size_t stride = (size_t)gridDim.x * blockDim.x;
    for (size_t i = (size_t)blockIdx.x * blockDim.x + threadIdx.x; i < n4; i += stride) {
        float4 v = *((const float4*)src + i);
        half2 h01 = __floats2half2_rn(v.x, v.y);
        half2 h23 = __floats2half2_rn(v.z, v.w);
        *(uint2*)(hi + i * 4) = make_uint2(*(uint32_t*)&h01, *(uint32_t*)&h23);
    }
}

// ---------------------------------------------------------------------------
// 1-term fp16 GEMM (NT): C = A * B^T + bias  (A,B fp16 RN).
// BM=BN=128, BK=64, 3-stage cp.async pipeline, 2 smem planes,
// row pitch 144B (conflict-free LDSM), 256 threads, 2 CTAs/SM.
// ---------------------------------------------------------------------------
#define GBM 128
#define GBK 64
#define GPITCH 144                        // bytes per 64-half row (128B data + 16 pad)
#define PL_BYTES (128 * GPITCH)           // 18432
#define BUF_BYTES (2 * PL_BYTES)          // 36864
#define NSTAGE 3
#define SM_GEMM_TOTAL (NSTAGE * BUF_BYTES)   // 110592

__global__ __launch_bounds__(256, 2)
void gemm_1t(const __half* __restrict__ A, const __half* __restrict__ B,
             const float* __restrict__ bias,
             float* __restrict__ Cf, __half* __restrict__ CH,
             int M, int N, int K, int outHalf)
{
    extern __shared__ char sm[];
    const uint32_t smb = smem_u32(sm);

    const int tid  = threadIdx.x;
    const int wid  = tid >> 5;
    const int lane = tid & 31;
    const int g = lane >> 2;
    const int c = lane & 3;
    const int wm = wid & 1;
    const int wn = wid >> 1;

    const int m0 = blockIdx.y * GBM;
    const int n0 = blockIdx.x * GBM;

    const __half* gA = A + (size_t)m0 * K;
    const __half* gB = B + (size_t)n0 * K;

    const int m_idx = lane >> 3;
    const int rin   = lane & 7;
    const uint32_t aRowOff = (uint32_t)(wm * 64 + (m_idx & 1) * 8 + rin) * GPITCH
                           + (uint32_t)(m_idx >> 1) * 16;
    const uint32_t bRowOff = (uint32_t)(wn * 32 + (m_idx >> 1) * 8 + rin) * GPITCH
                           + (uint32_t)(m_idx & 1) * 16;

    float acc[4][4][4];
    #pragma unroll
    for (int i = 0; i < 4; i++)
        #pragma unroll
        for (int j = 0; j < 4; j++)
            #pragma unroll
            for (int r = 0; r < 4; r++) acc[i][j][r] = 0.f;

    const int NK = K / GBK;   // 6

    // staging: 1024 16B-chunks per plane per stage; 4 per thread per plane
    auto stage = [&](int s, int kt) {
        const uint32_t dst = smb + (uint32_t)s * BUF_BYTES;
        const size_t go = (size_t)kt * GBK;
        #pragma unroll
        for (int cc = 0; cc < 4; cc++) {
            const int idx = tid + cc * 256;       // 0..1023
            const int row = idx >> 3, pos = idx & 7;
            const uint32_t d = dst + (uint32_t)row * GPITCH + (uint32_t)pos * 16;
            CP_ASYNC16(d + 0 * PL_BYTES, gA + (size_t)row * K + go + pos * 8);
            CP_ASYNC16(d + 1 * PL_BYTES, gB + (size_t)row * K + go + pos * 8);
        }
        CP_COMMIT();
    };

    stage(0, 0);
    stage(1, 1);

    int cur = 0, nx2 = 2;
    for (int kt = 0; kt < NK; kt++) {
        if (kt + 1 < NK) { CP_WAIT(1); } else { CP_WAIT(0); }
        __syncthreads();

        if (kt + 2 < NK) stage(nx2, kt + 2);

        const uint32_t bufB = smb + (uint32_t)cur * BUF_BYTES;

        #pragma unroll
        for (int ks = 0; ks < 4; ks++) {
            const uint32_t ko = (uint32_t)ks * 32;   // bytes (16 halves)

            uint32_t bfr[4][2];
            #pragma unroll
            for (int nn = 0; nn < 2; nn++) {
                uint32_t r4[4];
                ldmx4(r4, bufB + PL_BYTES + bRowOff + (uint32_t)nn * 16 * GPITCH + ko);
                bfr[2 * nn][0] = r4[0]; bfr[2 * nn][1] = r4[1];
                bfr[2 * nn + 1][0] = r4[2]; bfr[2 * nn + 1][1] = r4[3];
            }

            uint32_t af[4][4];
            #pragma unroll
            for (int tm = 0; tm < 4; tm++)
                ldmx4(af[tm], bufB + aRowOff + (uint32_t)tm * 16 * GPITCH + ko);

            #pragma unroll
            for (int tm = 0; tm < 4; tm++)
                #pragma unroll
                for (int tn = 0; tn < 4; tn++)
                    mma_f16(acc[tm][tn], af[tm], bfr[tn]);
        }

        cur = (cur == 2) ? 0 : cur + 1;
        nx2 = (nx2 == 2) ? 0 : nx2 + 1;
    }

    // ---- epilogue ----
    #pragma unroll
    for (int tm = 0; tm < 4; tm++) {
        const int r = m0 + wm * 64 + tm * 16 + g;
        #pragma unroll
        for (int tn = 0; tn < 4; tn++) {
            const int col = n0 + wn * 32 + tn * 8 + 2 * c;
            const float b0 = __ldg(&bias[col]);
            const float b1 = __ldg(&bias[col + 1]);
            const float o00 = acc[tm][tn][0] + b0, o01 = acc[tm][tn][1] + b1;
            const float o10 = acc[tm][tn][2] + b0, o11 = acc[tm][tn][3] + b1;
            if (outHalf) {
                // head-blocked layout: [(col>>5)][row][col&31]
                const size_t hb = (size_t)(col >> 5) * ((size_t)TOKENS * 32)
                                + (size_t)(col & 31);
                half2 h0 = __floats2half2_rn(o00, o01);
                half2 h1 = __floats2half2_rn(o10, o11);
                *(uint32_t*)(CH + hb + (size_t)r * 32)       = *(uint32_t*)&h0;
                *(uint32_t*)(CH + hb + (size_t)(r + 8) * 32) = *(uint32_t*)&h1;
            } else {
                *(float2*)(Cf + (size_t)r * N + col)       = make_float2(o00, o01);
                *(float2*)(Cf + (size_t)(r + 8) * N + col) = make_float2(o10, o11);
            }
        }
    }
}

// ---------------------------------------------------------------------------
// Tensor-core windowed attention (1-term fp16), 6 heads/block, double-buffered.
// Block = (bn, head-group of 6); 128 threads / 4 warps.
// ---------------------------------------------------------------------------
#define HPB 6
#define VPITCH 40
#define PPITCH 72
// per-buffer plane offsets (halves): Q, K, V
#define OFF_Q 0
#define OFF_K 2560
#define OFF_V 5120
#define BUF_HALVES 7680
// shared P plane (64 rows x 72) + bias cache
#define OFF_P 15360
#define OFF_SBIAS 19968          // 169 floats = 338 halves
#define SMEM_HALVES 20312
#define SM_ATTN_TOTAL (SMEM_HALVES * 2)   // 40624 bytes

__global__ __launch_bounds__(128)
void attn_mma(const __half* __restrict__ qkvH,
              const float* __restrict__ mask, const float* __restrict__ bias_table,
              __half* __restrict__ ctxH)
{
    extern __shared__ __half sh[];
    const uint32_t smb = smem_u32(sh);
    float* sbias = (float*)(sh + OFF_SBIAS);

    const int blk   = blockIdx.x;
    const int bn    = blk >> 1;
    const int hbase = (blk & 1) * HPB;
    const int tid = threadIdx.x;
    const int w    = tid >> 5;
    const int lane = tid & 31;
    const int g    = lane >> 2;
    const int cq   = lane & 3;
    const int m_idx = lane >> 3;
    const int rin   = lane & 7;

    // zero all smem once (pads must be 0)
    for (int i = tid; i < SMEM_HALVES / 8; i += 128)
        *(uint4*)(sh + (size_t)i * 8) = make_uint4(0u, 0u, 0u, 0u);
    __syncthreads();

    const size_t tokbase = (size_t)bn * NTOK;

    // coalesced head-slice gather: 3 planes x 49 rows x 4 chunks = 588 x 16B
    auto issue_qkv = [&](int head, int buf) {
        #pragma unroll 1
        for (int e = tid; e < 588; e += 128) {
            const int p  = e / 196;
            const int ch = e - p * 196;
            const int r  = ch >> 2;
            const int c4 = ch & 3;
            const __half* src = qkvH
                + (((size_t)(p * NHEADS + head) * TOKENS + tokbase + r) << 5) + c4 * 8;
            const uint32_t dst = smb + 2u * (uint32_t)(buf * BUF_HALVES + p * 2560
                               + r * VPITCH + c4 * 8);
            CP_ASYNC16(dst, src);
        }
        CP_COMMIT();
    };

    issue_qkv(hbase + 0, 0);
    issue_qkv(hbase + 1, 1);

    const float scale = 0.17677669529663687f;
    const float* mrow = mask + (size_t)(bn >> 6) * (NTOK * NTOK);

    for (int t = 0; t < HPB; t++) {
        const int h   = hbase + t;
        const uint32_t bofs = (uint32_t)((t & 1) * BUF_HALVES);

        if (t < HPB - 1) { CP_WAIT(1); } else { CP_WAIT(0); }
        for (int e = tid; e < 169; e += 128) sbias[e] = bias_table[e * NHEADS + h];
        __syncthreads();

        // ---- QK^T ----
        float acc[7][4];
        #pragma unroll
        for (int nt = 0; nt < 7; nt++)
            #pragma unroll
            for (int r = 0; r < 4; r++) acc[nt][r] = 0.f;

        uint32_t qf[2][4];
        #pragma unroll
        for (int kt = 0; kt < 2; kt++) {
            const uint32_t a = smb + 2u * (uint32_t)(bofs + OFF_Q
                             + (16 * w + (m_idx & 1) * 8 + rin) * VPITCH
                             + (m_idx >> 1) * 8 + kt * 16);
            ldmx4(qf[kt], a);
        }

        #pragma unroll
        for (int kt = 0; kt < 2; kt++)
            #pragma unroll
            for (int p = 0; p < 4; p++) {
                uint32_t r4[4];
                const uint32_t a = smb + 2u * (uint32_t)(bofs + OFF_K
                                 + (16 * p + (m_idx >> 1) * 8 + rin) * VPITCH
                                 + (m_idx & 1) * 8 + kt * 16);
                ldmx4(r4, a);
                uint32_t b0[2] = { r4[0], r4[1] };
                uint32_t b1[2] = { r4[2], r4[3] };
                mma_f16(acc[2 * p], qf[kt], b0);
                if (p < 3) mma_f16(acc[2 * p + 1], qf[kt], b1);
            }

        // ---- softmax in fragments ----
        const int i0 = 16 * w + g, i1 = i0 + 8;

        float sv[7][4];
        float mm0 = -1e30f, mm1 = -1e30f;
        #pragma unroll
        for (int nt = 0; nt < 7; nt++) {
            #pragma unroll
            for (int r = 0; r < 4; r++) {
                const int i = (r < 2) ? i0 : i1;
                const int j = 8 * nt + 2 * cq + (r & 1);
                float s;
                if (i >= NTOK) s = 0.f;
                else if (j >= NTOK) s = -1e30f;
                else {
                    const int ih = i / 7, iw = i - ih * 7;
                    const int jh = j / 7, jw = j - jh * 7;
                    const int ridx = (ih - jh + 6) * 13 + (iw - jw + 6);
                    s = acc[nt][r] * scale + sbias[ridx] + __ldg(&mrow[i * NTOK + j]);
                }
                sv[nt][r] = s;
                if (r < 2) mm0 = fmaxf(mm0, s); else mm1 = fmaxf(mm1, s);
            }
        }
        mm0 = fmaxf(mm0, __shfl_xor_sync(0xffffffffu, mm0, 1));
        mm0 = fmaxf(mm0, __shfl_xor_sync(0xffffffffu, mm0, 2));
        mm1 = fmaxf(mm1, __shfl_xor_sync(0xffffffffu, mm1, 1));
        mm1 = fmaxf(mm1, __shfl_xor_sync(0xffffffffu, mm1, 2));

        float s0 = 0.f, s1 = 0.f;
        #pragma unroll
        for (int nt = 0; nt < 7; nt++) {
            #pragma unroll
            for (int r = 0; r < 4; r++) {
                const int i = (r < 2) ? i0 : i1;
                const int j = 8 * nt + 2 * cq + (r & 1);
                const float e = __expf(sv[nt][r] - ((r < 2) ? mm0 : mm1));
                if (r < 2) s0 += e; else s1 += e;
                sh[OFF_P + i * PPITCH + j] = __float2half_rn(e);
            }
        }
        s0 += __shfl_xor_sync(0xffffffffu, s0, 1);
        s0 += __shfl_xor_sync(0xffffffffu, s0, 2);
        s1 += __shfl_xor_sync(0xffffffffu, s1, 1);
        s1 += __shfl_xor_sync(0xffffffffu, s1, 2);
        const float inv0 = 1.f / s0;
        const float inv1 = 1.f / s1;

        __syncthreads();

        // ---- PV ----
        float pv[4][4];
        #pragma unroll
        for (int nt = 0; nt < 4; nt++)
            #pragma unroll
            for (int r = 0; r < 4; r++) pv[nt][r] = 0.f;

        const uint32_t pARow = (uint32_t)((16 * w + (m_idx & 1) * 8 + rin) * PPITCH
                             + (m_idx >> 1) * 8);
        #pragma unroll
        for (int kt = 0; kt < 4; kt++) {
            uint32_t pf[4];
            ldmx4(pf, smb + 2u * (uint32_t)(OFF_P + pARow + kt * 16));
            #pragma unroll
            for (int dp = 0; dp < 2; dp++) {
                uint32_t vf[4];
                const uint32_t a = smb + 2u * (uint32_t)(bofs + OFF_V
                                 + (16 * kt + (m_idx & 1) * 8 + rin) * VPITCH
                                 + (m_idx >> 1) * 8 + dp * 16);
                ldmx4t(vf, a);
                uint32_t b0[2] = { vf[0], vf[1] };
                uint32_t b1[2] = { vf[2], vf[3] };
                mma_f16(pv[2 * dp], pf, b0);
                mma_f16(pv[2 * dp + 1], pf, b1);
            }
        }

        // ---- epilogue: normalize, store ctx fp16 ----
        const size_t ob = (size_t)bn * NTOK * DIM + (size_t)h * DHEAD;
        if (i0 < NTOK) {
            #pragma unroll
            for (int nt = 0; nt < 4; nt++) {
                const int d = 8 * nt + 2 * cq;
                half2 hv = __floats2half2_rn(pv[nt][0] * inv0, pv[nt][1] * inv0);
                *(uint32_t*)(ctxH + ob + (size_t)i0 * DIM + d) = *(uint32_t*)&hv;
            }
        }
        if (i1 < NTOK) {
            #pragma unroll
            for (int nt = 0; nt < 4; nt++) {
                const int d = 8 * nt + 2 * cq;
                half2 hv = __floats2half2_rn(pv[nt][2] * inv1, pv[nt][3] * inv1);
                *(uint32_t*)(ctxH + ob + (size_t)i1 * DIM + d) = *(uint32_t*)&hv;
            }
        }

        __syncthreads();

        if (t + 2 < HPB) issue_qkv(hbase + t + 2, t & 1);
    }
}

// ---------------------------------------------------------------------------
extern "C" void kernel_launch(void* const* d_in, const int* in_sizes, int n_in,
                              void* d_out, int out_size)
{
    const float* x          = (const float*)d_in[0];
    const float* mask       = (const float*)d_in[1];
    const float* w_qkv      = (const float*)d_in[2];
    const float* b_qkv      = (const float*)d_in[3];
    const float* w_proj     = (const float*)d_in[4];
    const float* b_proj     = (const float*)d_in[5];
    const float* bias_table = (const float*)d_in[6];
    float* out = (float*)d_out;

    __half *qkvH, *xH, *ctxH, *wqH, *wpH;
    cudaGetSymbolAddress((void**)&qkvH, g_qkvH);
    cudaGetSymbolAddress((void**)&xH,   g_xH);
    cudaGetSymbolAddress((void**)&ctxH, g_ctxH);
    cudaGetSymbolAddress((void**)&wqH,  g_wqkvH);
    cudaGetSymbolAddress((void**)&wpH,  g_wprojH);

    cudaFuncSetAttribute(gemm_1t, cudaFuncAttributeMaxDynamicSharedMemorySize, SM_GEMM_TOTAL);
    cudaFuncSetAttribute(attn_mma, cudaFuncAttributeMaxDynamicSharedMemorySize, SM_ATTN_TOTAL);

    // 0) prep: fp16 RN converts
    cvt_kernel<<<1184, 256>>>(x, xH, (size_t)TOKENS * DIM / 4);
    cvt_kernel<<<432, 256>>>(w_qkv, wqH, (size_t)QKV_COLS * DIM / 4);
    cvt_kernel<<<144, 256>>>(w_proj, wpH, (size_t)DIM * DIM / 4);

    // 1) QKV projection -> head-blocked fp16
    {
        dim3 grid(QKV_COLS / 128, TOKENS / 128);
        gemm_1t<<<grid, 256, SM_GEMM_TOTAL>>>(xH, wqH, b_qkv, nullptr, qkvH,
                                              TOKENS, QKV_COLS, DIM, 1);
    }
    // 2) tensor-core windowed attention
    attn_mma<<<BN_TOTAL * 2, 128, SM_ATTN_TOTAL>>>(qkvH, mask, bias_table, ctxH);
    // 3) output projection -> fp32 out
    {
        dim3 grid(DIM / 128, TOKENS / 128);
        gemm_1t<<<grid, 256, SM_GEMM_TOTAL>>>(ctxH, wpH, b_proj, out, nullptr,
                                              TOKENS, DIM, DIM, 0);
    }
}

// round 11
// speedup vs baseline: 4.6192x; 1.0160x over previous
#include <cuda_runtime.h>
#include <cuda_fp16.h>
#include <cstdint>
#include <cstddef>

// ---------------------------------------------------------------------------
// Problem constants
// ---------------------------------------------------------------------------
#define NHEADS   12
#define DHEAD    32
#define NTOK     49
#define DIM      384
#define BN_TOTAL 4096
#define TOKENS   (BN_TOTAL * NTOK)   // 200704
#define QKV_COLS 1152

// Scratch (allocation-free rule: device globals)
// qkv stored head-blocked: [(comp*12+head)][token][32]
__device__ __half g_qkvH[(size_t)TOKENS * QKV_COLS];
__device__ __half g_xH[(size_t)TOKENS * DIM];
__device__ __half g_ctxH[(size_t)TOKENS * DIM];
__device__ __half g_wqkvH[(size_t)QKV_COLS * DIM];
__device__ __half g_wprojH[(size_t)DIM * DIM];

// ---------------------------------------------------------------------------
// Common device helpers
// ---------------------------------------------------------------------------
__device__ __forceinline__ void mma_f16(float* d, const uint32_t* a, const uint32_t* b) {
    asm volatile(
        "mma.sync.aligned.m16n8k16.row.col.f32.f16.f16.f32 "
        "{%0,%1,%2,%3}, {%4,%5,%6,%7}, {%8,%9}, {%0,%1,%2,%3};"
        : "+f"(d[0]), "+f"(d[1]), "+f"(d[2]), "+f"(d[3])
        : "r"(a[0]), "r"(a[1]), "r"(a[2]), "r"(a[3]), "r"(b[0]), "r"(b[1]));
}

__device__ __forceinline__ void ldmx4(uint32_t* r, uint32_t addr) {
    asm volatile("ldmatrix.sync.aligned.m8n8.x4.shared.b16 {%0,%1,%2,%3}, [%4];"
        : "=r"(r[0]), "=r"(r[1]), "=r"(r[2]), "=r"(r[3]) : "r"(addr));
}
__device__ __forceinline__ void ldmx4t(uint32_t* r, uint32_t addr) {
    asm volatile("ldmatrix.sync.aligned.m8n8.x4.trans.shared.b16 {%0,%1,%2,%3}, [%4];"
        : "=r"(r[0]), "=r"(r[1]), "=r"(r[2]), "=r"(r[3]) : "r"(addr));
}

__device__ __forceinline__ uint32_t smem_u32(const void* p) {
    uint32_t a;
    asm("{ .reg .u64 t; cvta.to.shared.u64 t, %1; cvt.u32.u64 %0, t; }"
        : "=r"(a) : "l"(p));
    return a;
}

__device__ __forceinline__ uint32_t packh2(float a, float b) {
    half2 h = __floats2half2_rn(a, b);
    return *(uint32_t*)&h;
}

#define CP_ASYNC16(dst, src) \
    asm volatile("cp.async.cg.shared.global [%0], [%1], 16;" :: "r"(dst), "l"(src))
#define CP_COMMIT() asm volatile("cp.async.commit_group;" ::: "memory")
#define CP_WAIT(n)  asm volatile("cp.async.wait_group %0;" :: "n"(n) : "memory")

// ---------------------------------------------------------------------------
// Prep: fp32 -> fp16 RN convert, three arrays in one launch
// ---------------------------------------------------------------------------
__global__ void cvt3_kernel(const float* __restrict__ s0, __half* __restrict__ d0, size_t n0,
                            const float* __restrict__ s1, __half* __restrict__ d1, size_t n1,
                            const float* __restrict__ s2, __half* __restrict__ d2, size_t n2)
{
    const size_t total = n0 + n1 + n2;
    const size_t stride = (size_t)gridDim.x * blockDim.x;
    for (size_t i = (size_t)blockIdx.x * blockDim.x + threadIdx.x; i < total; i += stride) {
        const float* s; __half* d; size_t k;
        if (i < n0)           { s = s0; d = d0; k = i; }
        else if (i < n0 + n1) { s = s1; d = d1; k = i - n0; }
        else                  { s = s2; d = d2; k = i - n0 - n1; }
        float4 v = *((const float4*)s + k);
        *(uint2*)(d + k * 4) = make_uint2(packh2(v.x, v.y), packh2(v.z, v.w));
    }
}

// ---------------------------------------------------------------------------
// 1-term fp16 GEMM (NT): C = A * B^T + bias. Multi-tile blocks: each block
// processes MGRP m-tiles at fixed n-tile with a CONTINUOUS cp.async pipeline.
// BM=BN=128, BK=64, 3-stage, 2 smem planes, 256 threads, 2 CTAs/SM.
// ---------------------------------------------------------------------------
#define GBM 128
#define GBK 64
#define MGRP 4
#define GPITCH 144                        // bytes per 64-half row (128B data + 16 pad)
#define PL_BYTES (128 * GPITCH)           // 18432
#define BUF_BYTES (2 * PL_BYTES)          // 36864
#define NSTAGE 3
#define SM_GEMM_TOTAL (NSTAGE * BUF_BYTES)   // 110592

__global__ __launch_bounds__(256, 2)
void gemm_1t(const __half* __restrict__ A, const __half* __restrict__ B,
             const float* __restrict__ bias,
             float* __restrict__ Cf, __half* __restrict__ CH,
             int M, int N, int K, int outHalf)
{
    extern __shared__ char sm[];
    const uint32_t smb = smem_u32(sm);

    const int tid  = threadIdx.x;
    const int wid  = tid >> 5;
    const int lane = tid & 31;
    const int g = lane >> 2;
    const int c = lane & 3;
    const int wm = wid & 1;
    const int wn = wid >> 1;

    const int n0 = blockIdx.x * GBM;
    const __half* gB = B + (size_t)n0 * K;
    const __half* gA0 = A + (size_t)blockIdx.y * (MGRP * GBM) * K;

    const int m_idx = lane >> 3;
    const int rin   = lane & 7;
    const uint32_t aRowOff = (uint32_t)(wm * 64 + (m_idx & 1) * 8 + rin) * GPITCH
                           + (uint32_t)(m_idx >> 1) * 16;
    const uint32_t bRowOff = (uint32_t)(wn * 32 + (m_idx >> 1) * 8 + rin) * GPITCH
                           + (uint32_t)(m_idx & 1) * 16;

    float acc[4][4][4];
    #pragma unroll
    for (int i = 0; i < 4; i++)
        #pragma unroll
        for (int j = 0; j < 4; j++)
            #pragma unroll
            for (int r = 0; r < 4; r++) acc[i][j][r] = 0.f;

    const int NK = K / GBK;        // 6
    const int TS = NK * MGRP;      // 24

    // staging cursor
    int smt = 0, skt = 0;
    auto stage = [&](int s) {
        const __half* gAt = gA0 + (size_t)smt * GBM * K;
        const uint32_t dst = smb + (uint32_t)s * BUF_BYTES;
        const size_t go = (size_t)skt * GBK;
        #pragma unroll
        for (int cc = 0; cc < 4; cc++) {
            const int idx = tid + cc * 256;       // 0..1023
            const int row = idx >> 3, pos = idx & 7;
            const uint32_t d = dst + (uint32_t)row * GPITCH + (uint32_t)pos * 16;
            CP_ASYNC16(d + 0 * PL_BYTES, gAt + (size_t)row * K + go + pos * 8);
            CP_ASYNC16(d + 1 * PL_BYTES, gB  + (size_t)row * K + go + pos * 8);
        }
        CP_COMMIT();
        if (++skt == NK) { skt = 0; smt++; }
    };

    stage(0);
    stage(1);

    int cur = 0, nx2 = 2;
    int cmt = 0, ckt = 0;
    for (int s = 0; s < TS; s++) {
        if (s + 1 < TS) { CP_WAIT(1); } else { CP_WAIT(0); }
        __syncthreads();

        if (s + 2 < TS) stage(nx2);

        const uint32_t bufB = smb + (uint32_t)cur * BUF_BYTES;

        #pragma unroll
        for (int ks = 0; ks < 4; ks++) {
            const uint32_t ko = (uint32_t)ks * 32;   // bytes (16 halves)

            uint32_t bfr[4][2];
            #pragma unroll
            for (int nn = 0; nn < 2; nn++) {
                uint32_t r4[4];
                ldmx4(r4, bufB + PL_BYTES + bRowOff + (uint32_t)nn * 16 * GPITCH + ko);
                bfr[2 * nn][0] = r4[0]; bfr[2 * nn][1] = r4[1];
                bfr[2 * nn + 1][0] = r4[2]; bfr[2 * nn + 1][1] = r4[3];
            }

            uint32_t af[4][4];
            #pragma unroll
            for (int tm = 0; tm < 4; tm++)
                ldmx4(af[tm], bufB + aRowOff + (uint32_t)tm * 16 * GPITCH + ko);

            #pragma unroll
            for (int tm = 0; tm < 4; tm++)
                #pragma unroll
                for (int tn = 0; tn < 4; tn++)
                    mma_f16(acc[tm][tn], af[tm], bfr[tn]);
        }

        if (ckt == NK - 1) {
            // ---- epilogue for m-tile cmt ----
            const int m0 = (blockIdx.y * MGRP + cmt) * GBM;
            #pragma unroll
            for (int tm = 0; tm < 4; tm++) {
                const int r = m0 + wm * 64 + tm * 16 + g;
                #pragma unroll
                for (int tn = 0; tn < 4; tn++) {
                    const int col = n0 + wn * 32 + tn * 8 + 2 * c;
                    const float b0 = __ldg(&bias[col]);
                    const float b1 = __ldg(&bias[col + 1]);
                    const float o00 = acc[tm][tn][0] + b0, o01 = acc[tm][tn][1] + b1;
                    const float o10 = acc[tm][tn][2] + b0, o11 = acc[tm][tn][3] + b1;
                    if (outHalf) {
                        const size_t hb = (size_t)(col >> 5) * ((size_t)TOKENS * 32)
                                        + (size_t)(col & 31);
                        *(uint32_t*)(CH + hb + (size_t)r * 32)       = packh2(o00, o01);
                        *(uint32_t*)(CH + hb + (size_t)(r + 8) * 32) = packh2(o10, o11);
                    } else {
                        *(float2*)(Cf + (size_t)r * N + col)       = make_float2(o00, o01);
                        *(float2*)(Cf + (size_t)(r + 8) * N + col) = make_float2(o10, o11);
                    }
                    acc[tm][tn][0] = 0.f; acc[tm][tn][1] = 0.f;
                    acc[tm][tn][2] = 0.f; acc[tm][tn][3] = 0.f;
                }
            }
        }
        if (++ckt == NK) { ckt = 0; cmt++; }

        cur = (cur == 2) ? 0 : cur + 1;
        nx2 = (nx2 == 2) ? 0 : nx2 + 1;
    }
}

// ---------------------------------------------------------------------------
// Tensor-core windowed attention (1-term fp16), 6 heads/block, double-buffered,
// P kept entirely in registers (D-fragment == A-fragment identity).
// Block = (bn, head-group of 6); 128 threads / 4 warps.
// ---------------------------------------------------------------------------
#define HPB 6
#define VPITCH 40
// per-buffer plane offsets (halves): Q, K, V
#define OFF_Q 0
#define OFF_K 2560
#define OFF_V 5120
#define BUF_HALVES 7680
#define OFF_SBIAS 15360          // 169 floats = 338 halves
#define SMEM_HALVES 15704
#define SM_ATTN_TOTAL (SMEM_HALVES * 2)   // 31408 bytes

__global__ __launch_bounds__(128)
void attn_mma(const __half* __restrict__ qkvH,
              const float* __restrict__ mask, const float* __restrict__ bias_table,
              __half* __restrict__ ctxH)
{
    extern __shared__ __half sh[];
    const uint32_t smb = smem_u32(sh);
    float* sbias = (float*)(sh + OFF_SBIAS);

    const int blk   = blockIdx.x;
    const int bn    = blk >> 1;
    const int hbase = (blk & 1) * HPB;
    const int tid = threadIdx.x;
    const int w    = tid >> 5;
    const int lane = tid & 31;
    const int g    = lane >> 2;
    const int cq   = lane & 3;
    const int m_idx = lane >> 3;
    const int rin   = lane & 7;

    // zero all smem once (pads must be 0)
    for (int i = tid; i < SMEM_HALVES / 8; i += 128)
        *(uint4*)(sh + (size_t)i * 8) = make_uint4(0u, 0u, 0u, 0u);
    __syncthreads();

    const size_t tokbase = (size_t)bn * NTOK;

    // coalesced head-slice gather: 3 planes x 49 rows x 4 chunks = 588 x 16B
    auto issue_qkv = [&](int head, int buf) {
        #pragma unroll 1
        for (int e = tid; e < 588; e += 128) {
            const int p  = e / 196;
            const int ch = e - p * 196;
            const int r  = ch >> 2;
            const int c4 = ch & 3;
            const __half* src = qkvH
                + (((size_t)(p * NHEADS + head) * TOKENS + tokbase + r) << 5) + c4 * 8;
            const uint32_t dst = smb + 2u * (uint32_t)(buf * BUF_HALVES + p * 2560
                               + r * VPITCH + c4 * 8);
            CP_ASYNC16(dst, src);
        }
        CP_COMMIT();
    };

    issue_qkv(hbase + 0, 0);
    issue_qkv(hbase + 1, 1);

    const float scale = 0.17677669529663687f;
    const float* mrow = mask + (size_t)(bn >> 6) * (NTOK * NTOK);

    for (int t = 0; t < HPB; t++) {
        const int h   = hbase + t;
        const uint32_t bofs = (uint32_t)((t & 1) * BUF_HALVES);

        if (t < HPB - 1) { CP_WAIT(1); } else { CP_WAIT(0); }
        for (int e = tid; e < 169; e += 128) sbias[e] = bias_table[e * NHEADS + h];
        __syncthreads();

        // ---- QK^T ----
        float acc[7][4];
        #pragma unroll
        for (int nt = 0; nt < 7; nt++)
            #pragma unroll
            for (int r = 0; r < 4; r++) acc[nt][r] = 0.f;

        uint32_t qf[2][4];
        #pragma unroll
        for (int kt = 0; kt < 2; kt++) {
            const uint32_t a = smb + 2u * (uint32_t)(bofs + OFF_Q
                             + (16 * w + (m_idx & 1) * 8 + rin) * VPITCH
                             + (m_idx >> 1) * 8 + kt * 16);
            ldmx4(qf[kt], a);
        }

        #pragma unroll
        for (int kt = 0; kt < 2; kt++)
            #pragma unroll
            for (int p = 0; p < 4; p++) {
                uint32_t r4[4];
                const uint32_t a = smb + 2u * (uint32_t)(bofs + OFF_K
                                 + (16 * p + (m_idx >> 1) * 8 + rin) * VPITCH
                                 + (m_idx & 1) * 8 + kt * 16);
                ldmx4(r4, a);
                uint32_t b0[2] = { r4[0], r4[1] };
                uint32_t b1[2] = { r4[2], r4[3] };
                mma_f16(acc[2 * p], qf[kt], b0);
                if (p < 3) mma_f16(acc[2 * p + 1], qf[kt], b1);
            }

        // ---- softmax in fragments (e-values overwrite acc) ----
        const int i0 = 16 * w + g, i1 = i0 + 8;

        float mm0 = -1e30f, mm1 = -1e30f;
        #pragma unroll
        for (int nt = 0; nt < 7; nt++) {
            #pragma unroll
            for (int r = 0; r < 4; r++) {
                const int i = (r < 2) ? i0 : i1;
                const int j = 8 * nt + 2 * cq + (r & 1);
                float s;
                if (i >= NTOK) s = 0.f;
                else if (j >= NTOK) s = -1e30f;
                else {
                    const int ih = i / 7, iw = i - ih * 7;
                    const int jh = j / 7, jw = j - jh * 7;
                    const int ridx = (ih - jh + 6) * 13 + (iw - jw + 6);
                    s = acc[nt][r] * scale + sbias[ridx] + __ldg(&mrow[i * NTOK + j]);
                }
                acc[nt][r] = s;
                if (r < 2) mm0 = fmaxf(mm0, s); else mm1 = fmaxf(mm1, s);
            }
        }
        mm0 = fmaxf(mm0, __shfl_xor_sync(0xffffffffu, mm0, 1));
        mm0 = fmaxf(mm0, __shfl_xor_sync(0xffffffffu, mm0, 2));
        mm1 = fmaxf(mm1, __shfl_xor_sync(0xffffffffu, mm1, 1));
        mm1 = fmaxf(mm1, __shfl_xor_sync(0xffffffffu, mm1, 2));

        float s0 = 0.f, s1 = 0.f;
        #pragma unroll
        for (int nt = 0; nt < 7; nt++) {
            #pragma unroll
            for (int r = 0; r < 4; r++) {
                const float e = __expf(acc[nt][r] - ((r < 2) ? mm0 : mm1));
                if (r < 2) s0 += e; else s1 += e;
                acc[nt][r] = e;
            }
        }
        s0 += __shfl_xor_sync(0xffffffffu, s0, 1);
        s0 += __shfl_xor_sync(0xffffffffu, s0, 2);
        s1 += __shfl_xor_sync(0xffffffffu, s1, 1);
        s1 += __shfl_xor_sync(0xffffffffu, s1, 2);
        const float inv0 = 1.f / s0;
        const float inv1 = 1.f / s1;

        // ---- PV: P fragments built directly from acc registers ----
        float pv[4][4];
        #pragma unroll
        for (int nt = 0; nt < 4; nt++)
            #pragma unroll
            for (int r = 0; r < 4; r++) pv[nt][r] = 0.f;

        #pragma unroll
        for (int kt = 0; kt < 4; kt++) {
            uint32_t pf[4];
            pf[0] = packh2(acc[2 * kt][0], acc[2 * kt][1]);
            pf[1] = packh2(acc[2 * kt][2], acc[2 * kt][3]);
            if (2 * kt + 1 < 7) {
                pf[2] = packh2(acc[2 * kt + 1][0], acc[2 * kt + 1][1]);
                pf[3] = packh2(acc[2 * kt + 1][2], acc[2 * kt + 1][3]);
            } else {
                pf[2] = 0u; pf[3] = 0u;
            }
            #pragma unroll
            for (int dp = 0; dp < 2; dp++) {
                uint32_t vf[4];
                const uint32_t a = smb + 2u * (uint32_t)(bofs + OFF_V
                                 + (16 * kt + (m_idx & 1) * 8 + rin) * VPITCH
                                 + (m_idx >> 1) * 8 + dp * 16);
                ldmx4t(vf, a);
                uint32_t b0[2] = { vf[0], vf[1] };
                uint32_t b1[2] = { vf[2], vf[3] };
                mma_f16(pv[2 * dp], pf, b0);
                mma_f16(pv[2 * dp + 1], pf, b1);
            }
        }

        // ---- epilogue: normalize, store ctx fp16 ----
        const size_t ob = (size_t)bn * NTOK * DIM + (size_t)h * DHEAD;
        if (i0 < NTOK) {
            #pragma unroll
            for (int nt = 0; nt < 4; nt++) {
                const int d = 8 * nt + 2 * cq;
                *(uint32_t*)(ctxH + ob + (size_t)i0 * DIM + d)
                    = packh2(pv[nt][0] * inv0, pv[nt][1] * inv0);
            }
        }
        if (i1 < NTOK) {
            #pragma unroll
            for (int nt = 0; nt < 4; nt++) {
                const int d = 8 * nt + 2 * cq;
                *(uint32_t*)(ctxH + ob + (size_t)i1 * DIM + d)
                    = packh2(pv[nt][2] * inv1, pv[nt][3] * inv1);
            }
        }

        __syncthreads();   // all reads of buffer + sbias done

        if (t + 2 < HPB) issue_qkv(hbase + t + 2, t & 1);
    }
}

// ---------------------------------------------------------------------------
extern "C" void kernel_launch(void* const* d_in, const int* in_sizes, int n_in,
                              void* d_out, int out_size)
{
    const float* x          = (const float*)d_in[0];
    const float* mask       = (const float*)d_in[1];
    const float* w_qkv      = (const float*)d_in[2];
    const float* b_qkv      = (const float*)d_in[3];
    const float* w_proj     = (const float*)d_in[4];
    const float* b_proj     = (const float*)d_in[5];
    const float* bias_table = (const float*)d_in[6];
    float* out = (float*)d_out;

    __half *qkvH, *xH, *ctxH, *wqH, *wpH;
    cudaGetSymbolAddress((void**)&qkvH, g_qkvH);
    cudaGetSymbolAddress((void**)&xH,   g_xH);
    cudaGetSymbolAddress((void**)&ctxH, g_ctxH);
    cudaGetSymbolAddress((void**)&wqH,  g_wqkvH);
    cudaGetSymbolAddress((void**)&wpH,  g_wprojH);

    cudaFuncSetAttribute(gemm_1t, cudaFuncAttributeMaxDynamicSharedMemorySize, SM_GEMM_TOTAL);
    cudaFuncSetAttribute(attn_mma, cudaFuncAttributeMaxDynamicSharedMemorySize, SM_ATTN_TOTAL);

    // 0) prep: fp16 RN converts (single launch)
    cvt3_kernel<<<1480, 256>>>(x, xH, (size_t)TOKENS * DIM / 4,
                               w_qkv, wqH, (size_t)QKV_COLS * DIM / 4,
                               w_proj, wpH, (size_t)DIM * DIM / 4);

    // 1) QKV projection -> head-blocked fp16
    {
        dim3 grid(QKV_COLS / 128, TOKENS / (128 * MGRP));
        gemm_1t<<<grid, 256, SM_GEMM_TOTAL>>>(xH, wqH, b_qkv, nullptr, qkvH,
                                              TOKENS, QKV_COLS, DIM, 1);
    }
    // 2) tensor-core windowed attention
    attn_mma<<<BN_TOTAL * 2, 128, SM_ATTN_TOTAL>>>(qkvH, mask, bias_table, ctxH);
    // 3) output projection -> fp32 out
    {
        dim3 grid(DIM / 128, TOKENS / (128 * MGRP));
        gemm_1t<<<grid, 256, SM_GEMM_TOTAL>>>(ctxH, wpH, b_proj, out, nullptr,
                                              TOKENS, DIM, DIM, 0);
    }
}